// round 4
// baseline (speedup 1.0000x reference)
#include <cuda_runtime.h>
#include <cstdint>
#include <math.h>

#define Bq    8
#define Sq    512
#define Dm    768
#define Hh    12
#define Dk    64
#define BHn   (Bq*Hh)            // 96
#define Mrows (Bq*Sq)            // 4096
#define NATT  (25165824)         // B*H*S*S
#define SCALE 0.036084391824351615f   // 1/sqrt(768)

// ---- mma.sync tf32 GEMM tiling ----
#define BM 128
#define BN 64
#define BK 32
#define ASTR 36                        // padded k-stride (floats), conflict-free
#define A_BYTES (BM*ASTR*4)            // 18432
#define B_BYTES (BN*ASTR*4)            // 9216
#define STAGE_B (A_BYTES + B_BYTES)    // 27648
#define DYN_SMEM (2*STAGE_B)           // 55296
#define NSTAGE (Dm/BK)                 // 24

// Scratch (device globals: allocation-free, graph-capturable)
__device__ float  g_proj[(size_t)6 * Mrows * Dm];   // ql,kl,qr,kr,q,k
__device__ float  g_wT[(size_t)6 * Dm * Dm];        // W transposed: wT[n][k]
__device__ double g_loss;

struct Ptr6 { const float* p[6]; };

// ---------------------------------------------------------------------------
// helpers
// ---------------------------------------------------------------------------
__device__ __forceinline__ uint32_t smem_u32(const void* p) {
    uint32_t a;
    asm("{ .reg .u64 t; cvta.to.shared.u64 t, %1; cvt.u32.u64 %0, t; }"
        : "=r"(a) : "l"(p));
    return a;
}
__device__ __forceinline__ void cp16(uint32_t s, const void* g) {
    asm volatile("cp.async.ca.shared.global [%0], [%1], 16;"
                 :: "r"(s), "l"(g) : "memory");
}
__device__ __forceinline__ void cp_commit() {
    asm volatile("cp.async.commit_group;" ::: "memory");
}
template <int N>
__device__ __forceinline__ void cp_wait() {
    asm volatile("cp.async.wait_group %0;" :: "n"(N) : "memory");
}
__device__ __forceinline__ void split_tf32(float a, uint32_t& hi, uint32_t& lo) {
    uint32_t h;
    asm("cvt.rna.tf32.f32 %0, %1;" : "=r"(h) : "f"(a));
    float r = a - __uint_as_float(h);
    uint32_t l;
    asm("cvt.rna.tf32.f32 %0, %1;" : "=r"(l) : "f"(r));
    hi = h; lo = l;
}
__device__ __forceinline__ void mma8(float* c, const uint32_t* a, const uint32_t* b) {
    asm volatile(
        "mma.sync.aligned.m16n8k8.row.col.f32.tf32.tf32.f32 "
        "{%0,%1,%2,%3}, {%4,%5,%6,%7}, {%8,%9}, {%0,%1,%2,%3};"
        : "+f"(c[0]), "+f"(c[1]), "+f"(c[2]), "+f"(c[3])
        : "r"(a[0]), "r"(a[1]), "r"(a[2]), "r"(a[3]), "r"(b[0]), "r"(b[1]));
}
// ln(1+e^-p) for p in [0,1], no MUFU: ln2 - p/2 + lncosh(p/2) (Taylor, err ~1.5e-8)
__device__ __forceinline__ float softplus_neg01(float p) {
    float x = 0.5f * p;
    float y = x * x;
    float lc = y * (0.5f + y * (-8.3333333333e-2f + y * (2.2222222222e-2f +
               y * (-6.7460317460e-3f + y * (2.1869488536e-3f +
               y * (-7.3860295563e-4f))))));
    return 0.69314718056f - x + lc;
}

// ---------------------------------------------------------------------------
// Transpose all 6 weight matrices: g_wT[w][n][k] = W[w][k][n]
// ---------------------------------------------------------------------------
__global__ void transpose6(Ptr6 ws) {
    __shared__ float t[32][33];
    int w = blockIdx.z;
    const float* W = ws.p[w];
    float* T = g_wT + (size_t)w * Dm * Dm;
    int n0 = blockIdx.x * 32, k0 = blockIdx.y * 32;
#pragma unroll
    for (int i = 0; i < 4; i++)
        t[threadIdx.y + i * 8][threadIdx.x] =
            W[(size_t)(k0 + threadIdx.y + i * 8) * Dm + n0 + threadIdx.x];
    __syncthreads();
#pragma unroll
    for (int i = 0; i < 4; i++)
        T[(size_t)(n0 + threadIdx.y + i * 8) * Dm + k0 + threadIdx.x] =
            t[threadIdx.x][threadIdx.y + i * 8];
}

// ---------------------------------------------------------------------------
// mma.sync tf32 GEMM (3x split): C = (A @ W + bias) * scale
// grid (32 m, 12 n, 6 gemms), 256 threads, cp.async double-buffered
// ---------------------------------------------------------------------------
__global__ __launch_bounds__(256, 2) void gemm_mma(const float* __restrict__ query,
                                                   const float* __restrict__ key,
                                                   Ptr6 biases)
{
    extern __shared__ char dsm[];
    const int tid = threadIdx.x, warp = tid >> 5, lane = tid & 31;
    const int g = lane >> 2, t = lane & 3;
    const int wm = (warp >> 1) * 32, wn = (warp & 1) * 32;

    const int w = blockIdx.z;
    const float* A  = (w & 1) ? key : query;
    const float* Wt = g_wT + (size_t)w * Dm * Dm;
    float* C        = g_proj + (size_t)w * Mrows * Dm;
    const float* bias = biases.p[w];
    const float scale = (w & 1) ? 1.0f : SCALE;
    const int m0 = blockIdx.x * BM, n0 = blockIdx.y * BN;

    const uint32_t sb = smem_u32(dsm);

    auto load_stage = [&](int s, int buf) {
        const int kk = s * BK;
        const uint32_t ab = sb + buf * STAGE_B;
        const uint32_t bb = ab + A_BYTES;
#pragma unroll
        for (int i = 0; i < 4; i++) {          // A: 128x32 floats
            int li = i * 256 + tid;
            int row = li >> 3, kq = (li & 7) * 4;
            cp16(ab + (uint32_t)(row * ASTR + kq) * 4,
                 &A[(size_t)(m0 + row) * Dm + kk + kq]);
        }
#pragma unroll
        for (int i = 0; i < 2; i++) {          // B: 64x32 floats
            int li = i * 256 + tid;
            int row = li >> 3, kq = (li & 7) * 4;
            cp16(bb + (uint32_t)(row * ASTR + kq) * 4,
                 &Wt[(size_t)(n0 + row) * Dm + kk + kq]);
        }
        cp_commit();
    };

    float acc[2][4][4];
#pragma unroll
    for (int mf = 0; mf < 2; mf++)
#pragma unroll
        for (int nf = 0; nf < 4; nf++)
#pragma unroll
            for (int i = 0; i < 4; i++) acc[mf][nf][i] = 0.0f;

    load_stage(0, 0);

    for (int s = 0; s < NSTAGE; s++) {
        if (s + 1 < NSTAGE) { load_stage(s + 1, (s + 1) & 1); cp_wait<1>(); }
        else                { cp_wait<0>(); }
        __syncthreads();

        const int buf = s & 1;
        const float* As = (const float*)(dsm + buf * STAGE_B);
        const float* Bs = (const float*)(dsm + buf * STAGE_B + A_BYTES);

#pragma unroll
        for (int ks = 0; ks < 4; ks++) {
            const int kq = ks * 8;
            uint32_t ah[2][4], al[2][4], bh[4][2], bl[4][2];
#pragma unroll
            for (int mf = 0; mf < 2; mf++) {
                int r0 = wm + mf * 16 + g;
                split_tf32(As[r0 * ASTR + kq + t],           ah[mf][0], al[mf][0]);
                split_tf32(As[(r0 + 8) * ASTR + kq + t],     ah[mf][1], al[mf][1]);
                split_tf32(As[r0 * ASTR + kq + t + 4],       ah[mf][2], al[mf][2]);
                split_tf32(As[(r0 + 8) * ASTR + kq + t + 4], ah[mf][3], al[mf][3]);
            }
#pragma unroll
            for (int nf = 0; nf < 4; nf++) {
                int n = wn + nf * 8 + g;
                split_tf32(Bs[n * ASTR + kq + t],     bh[nf][0], bl[nf][0]);
                split_tf32(Bs[n * ASTR + kq + t + 4], bh[nf][1], bl[nf][1]);
            }
#pragma unroll
            for (int mf = 0; mf < 2; mf++)
#pragma unroll
                for (int nf = 0; nf < 4; nf++) {
                    mma8(acc[mf][nf], ah[mf], bh[nf]);
                    mma8(acc[mf][nf], ah[mf], bl[nf]);
                    mma8(acc[mf][nf], al[mf], bh[nf]);
                }
        }
        __syncthreads();
    }

    // Epilogue: c frag rows {g, g+8}, cols {2t, 2t+1} within each m16n8 tile
#pragma unroll
    for (int mf = 0; mf < 2; mf++) {
        int row0 = m0 + wm + mf * 16 + g;
#pragma unroll
        for (int nf = 0; nf < 4; nf++) {
            int col = n0 + wn + nf * 8 + 2 * t;
            float2 bv = *(const float2*)&bias[col];
            float2 o0, o1;
            o0.x = (acc[mf][nf][0] + bv.x) * scale;
            o0.y = (acc[mf][nf][1] + bv.y) * scale;
            o1.x = (acc[mf][nf][2] + bv.x) * scale;
            o1.y = (acc[mf][nf][3] + bv.y) * scale;
            *(float2*)&C[(size_t)row0 * Dm + col]       = o0;
            *(float2*)&C[(size_t)(row0 + 8) * Dm + col] = o1;
        }
    }
}

// ---------------------------------------------------------------------------
// Fused attention: per-(bh, 16-q-row tile) block, 512 threads, 2 q-rows/thread.
// Softmask in registers; warp-level triangle skipping for modes 0/1;
// BCE via MUFU-free softplus polynomial.
// ---------------------------------------------------------------------------
__global__ __launch_bounds__(512) void attn_fused(
    const float* __restrict__ mask,
    const float* __restrict__ span, float* __restrict__ out)
{
    __shared__ float sQ[16][64];
    __shared__ float sKT[16][512];
    __shared__ float sRed[16][2];
    __shared__ float sW[16];

    int tid  = threadIdx.x;
    int lane = tid & 31;
    int warp = tid >> 5;       // 0..15
    int half = warp & 1;       // which 256-col half this warp covers
    int qg   = tid >> 6;       // 0..7 -> q-group (2 rows each)
    int kg   = tid & 63;       // 0..63 -> 8 consecutive cols each
    int bh = blockIdx.y;
    int b = bh / Hh, h = bh % Hh;
    int q0 = blockIdx.x * 16;

    const int qmin = q0 + qg * 2, qmax = qmin + 1;
    const int c_lo = half * 256, c_hi = c_lo + 255;

    float smk[2][8];     // running soft mask (cumsum products), per-thread

    float rmk[8], rmq[2];
#pragma unroll
    for (int c = 0; c < 8; c++) {
        float mv = mask[b * Sq + kg * 8 + c];
        rmk[c] = (mv == -10000.0f) ? 1.0e9f : mv;
    }
#pragma unroll
    for (int r = 0; r < 2; r++) {
        float mv = mask[b * Sq + qmin + r];
        rmq[r] = (mv == -10000.0f) ? 1.0e9f : mv;
    }

    for (int mode = 0; mode < 3; mode++) {
        const float* Ap = g_proj + (size_t)(mode * 2)     * Mrows * Dm;
        const float* Bp = g_proj + (size_t)(mode * 2 + 1) * Mrows * Dm;

        // warp-uniform: this warp's entire 256-col span is boundary-masked
        const bool skipw = (mode == 0 && c_lo > qmax) ||
                           (mode == 1 && c_hi < qmin);

        __syncthreads();
        if (tid < 256) {
            int row = tid >> 4;
            int d4  = (tid & 15) * 4;
            *(float4*)&sQ[row][d4] =
                *(const float4*)&Ap[((size_t)(b * Sq + q0 + row)) * Dm + h * Dk + d4];
        }

        float acc[2][8];
#pragma unroll
        for (int r = 0; r < 2; r++)
#pragma unroll
            for (int c = 0; c < 8; c++) acc[r][c] = 0.0f;

        for (int dc = 0; dc < 4; dc++) {
            __syncthreads();
#pragma unroll
            for (int i = 0; i < 4; i++) {
                int lin = i * 512 + tid;
                int tok = lin >> 2;
                int f4  = (lin & 3) * 4;
                float4 v = *(const float4*)&Bp[((size_t)(b * Sq + tok)) * Dm + h * Dk + dc * 16 + f4];
                sKT[f4 + 0][tok] = v.x; sKT[f4 + 1][tok] = v.y;
                sKT[f4 + 2][tok] = v.z; sKT[f4 + 3][tok] = v.w;
            }
            __syncthreads();
            if (skipw) continue;   // scores unused: exp==0, cumsum contribution 0
#pragma unroll
            for (int dd = 0; dd < 16; dd++) {
                float4 k0 = *(const float4*)&sKT[dd][kg * 8];
                float4 k1 = *(const float4*)&sKT[dd][kg * 8 + 4];
#pragma unroll
                for (int r = 0; r < 2; r++) {
                    float qv = sQ[qg * 2 + r][dc * 16 + dd];
                    acc[r][0] += qv * k0.x; acc[r][1] += qv * k0.y;
                    acc[r][2] += qv * k0.z; acc[r][3] += qv * k0.w;
                    acc[r][4] += qv * k1.x; acc[r][5] += qv * k1.y;
                    acc[r][6] += qv * k1.z; acc[r][7] += qv * k1.w;
                }
            }
        }
        __syncthreads();

        // transform + per-row max
#pragma unroll
        for (int r = 0; r < 2; r++) {
            int q = qmin + r;
            float m;
            if (skipw) {
                m = -3.0e38f;
            } else {
                if (mode == 0) {
#pragma unroll
                    for (int c = 0; c < 8; c++)
                        if (kg * 8 + c > q) acc[r][c] -= 1.0e9f;
                } else if (mode == 1) {
#pragma unroll
                    for (int c = 0; c < 8; c++)
                        if (kg * 8 + c < q) acc[r][c] -= 1.0e9f;
                } else {
#pragma unroll
                    for (int c = 0; c < 8; c++)
                        acc[r][c] = (acc[r][c] - rmq[r] - rmk[c]) * smk[r][c];
                }
                m = acc[r][0];
#pragma unroll
                for (int c = 1; c < 8; c++) m = fmaxf(m, acc[r][c]);
#pragma unroll
                for (int off = 16; off >= 1; off >>= 1)
                    m = fmaxf(m, __shfl_xor_sync(0xffffffffu, m, off));
            }
            if (lane == 0) sRed[qg * 2 + r][half] = m;
        }
        __syncthreads();
        float mrow[2];
#pragma unroll
        for (int r = 0; r < 2; r++)
            mrow[r] = fmaxf(sRed[qg * 2 + r][0], sRed[qg * 2 + r][1]);
        __syncthreads();

        if (mode < 2) {
            float tval[2];
#pragma unroll
            for (int r = 0; r < 2; r++) {
                if (skipw) {
#pragma unroll
                    for (int c = 0; c < 8; c++) acc[r][c] = 0.0f;
                    tval[r] = 0.0f;
                    if (lane == 31) sRed[qg * 2 + r][half] = 0.0f;
                } else {
                    float run = 0.0f;
#pragma unroll
                    for (int c = 0; c < 8; c++) {
                        run += __expf(acc[r][c] - mrow[r]);
                        acc[r][c] = run;                 // local inclusive cumsum
                    }
                    float tv = run;
#pragma unroll
                    for (int off = 1; off < 32; off <<= 1) {
                        float u = __shfl_up_sync(0xffffffffu, tv, off);
                        if (lane >= off) tv += u;
                    }
                    tval[r] = tv;                         // inclusive total within warp
                    if (lane == 31) sRed[qg * 2 + r][half] = tv;
                }
            }
            __syncthreads();
#pragma unroll
            for (int r = 0; r < 2; r++) {
                float w0 = sRed[qg * 2 + r][0], w1 = sRed[qg * 2 + r][1];
                float sumrow = w0 + w1;
                float tot = acc[r][7];
                float excl = (half ? w0 : 0.0f) + (tval[r] - tot);
                float inv = 1.0f / sumrow;
                if (mode == 0) {
#pragma unroll
                    for (int c = 0; c < 8; c++)
                        smk[r][c] = (excl + acc[r][c]) * inv;
                } else {
                    // rev_incl[c] = sumrow - excl - local_incl[c-1]
                    float base = sumrow - excl;
                    smk[r][0] *= base * inv;
#pragma unroll
                    for (int c = 1; c < 8; c++)
                        smk[r][c] *= (base - acc[r][c - 1]) * inv;
                }
            }
        } else {
            float lsum = 0.0f;
#pragma unroll
            for (int r = 0; r < 2; r++) {
                float s = 0.0f;
#pragma unroll
                for (int c = 0; c < 8; c++) {
                    acc[r][c] = __expf(acc[r][c] - mrow[r]);
                    s += acc[r][c];
                }
#pragma unroll
                for (int off = 16; off >= 1; off >>= 1)
                    s += __shfl_xor_sync(0xffffffffu, s, off);
                if (lane == 0) sRed[qg * 2 + r][half] = s;
            }
            __syncthreads();
#pragma unroll
            for (int r = 0; r < 2; r++) {
                int q = qmin + r;
                float inv = 1.0f / (sRed[qg * 2 + r][0] + sRed[qg * 2 + r][1]);
                size_t oidx = ((size_t)bh * Sq + q) * Sq + kg * 8;
                size_t sidx = ((size_t)((h * Bq + b) * Sq + q)) * Sq + kg * 8;
                float4 sp0 = *(const float4*)&span[sidx];
                float4 sp1 = *(const float4*)&span[sidx + 4];
                float sp[8] = {sp0.x, sp0.y, sp0.z, sp0.w, sp1.x, sp1.y, sp1.z, sp1.w};
                float p[8];
#pragma unroll
                for (int c = 0; c < 8; c++) p[c] = acc[r][c] * inv;
                float4 o0 = {p[0], p[1], p[2], p[3]};
                float4 o1 = {p[4], p[5], p[6], p[7]};
                *(float4*)&out[oidx]     = o0;
                *(float4*)&out[oidx + 4] = o1;
                // bce = ln(1+e^-p) + p*(1-span)   (MUFU-free softplus)
#pragma unroll
                for (int c = 0; c < 8; c++)
                    lsum += softplus_neg01(p[c]) + p[c] * (1.0f - sp[c]);
            }
#pragma unroll
            for (int off = 16; off >= 1; off >>= 1)
                lsum += __shfl_xor_sync(0xffffffffu, lsum, off);
            __syncthreads();
            if (lane == 0) sW[warp] = lsum;
            __syncthreads();
            if (tid == 0) {
                float tot = 0.0f;
#pragma unroll
                for (int ww = 0; ww < 16; ww++) tot += sW[ww];
                atomicAdd(&g_loss, (double)tot);
            }
        }
    }
}

__global__ void zero_loss_kernel() { g_loss = 0.0; }

__global__ void finalize_kernel(float* out, int out_size) {
    if (out_size > NATT)
        out[NATT] = (float)(g_loss / (double)NATT);
}

// ---------------------------------------------------------------------------
extern "C" void kernel_launch(void* const* d_in, const int* in_sizes, int n_in,
                              void* d_out, int out_size)
{
    (void)in_sizes; (void)n_in;
    const float* query = (const float*)d_in[0];
    const float* key   = (const float*)d_in[1];
    const float* mask  = (const float*)d_in[2];
    const float* span  = (const float*)d_in[3];
    float* out = (float*)d_out;

    Ptr6 ws, bs;
    for (int w = 0; w < 6; w++) {
        ws.p[w] = (const float*)d_in[4 + 2 * w];
        bs.p[w] = (const float*)d_in[5 + 2 * w];
    }

    cudaFuncSetAttribute(gemm_mma, cudaFuncAttributeMaxDynamicSharedMemorySize, DYN_SMEM);

    transpose6<<<dim3(Dm / 32, Dm / 32, 6), dim3(32, 8)>>>(ws);
    gemm_mma<<<dim3(Mrows / BM, Dm / BN, 6), 256, DYN_SMEM>>>(query, key, bs);
    zero_loss_kernel<<<1, 1>>>();
    attn_fused<<<dim3(Sq / 16, BHn), 512>>>(mask, span, out);
    finalize_kernel<<<1, 1>>>(out, out_size);
}

// round 5
// speedup vs baseline: 1.1557x; 1.1557x over previous
#include <cuda_runtime.h>
#include <cstdint>
#include <math.h>

#define Bq    8
#define Sq    512
#define Dm    768
#define Hh    12
#define Dk    64
#define BHn   (Bq*Hh)            // 96
#define Mrows (Bq*Sq)            // 4096
#define NATT  (25165824)         // B*H*S*S
#define SCALE 0.036084391824351615f   // 1/sqrt(768)

// ---- mma.sync tf32 GEMM tiling ----
#define BM 128
#define BN 64
#define BK 32
#define ASTR 36                        // padded k-stride (floats), conflict-free
#define A_BYTES (BM*ASTR*4)            // 18432
#define BP_BYTES (BN*ASTR*4)           // 9216 per plane
#define B_BYTES (2*BP_BYTES)           // 18432 (hi+lo planes)
#define STAGE_B (A_BYTES + B_BYTES)    // 36864
#define DYN_SMEM (2*STAGE_B)           // 73728
#define NSTAGE (Dm/BK)                 // 24

// Scratch (device globals: allocation-free, graph-capturable)
__device__ float  g_proj[(size_t)6 * Mrows * Dm];     // ql,kl,qr,kr,q,k
__device__ float  g_wT[(size_t)6 * 2 * Dm * Dm];      // per w: hi plane, lo plane (n-major)
__device__ double g_loss;

struct Ptr6 { const float* p[6]; };

// ---------------------------------------------------------------------------
// helpers
// ---------------------------------------------------------------------------
__device__ __forceinline__ uint32_t smem_u32(const void* p) {
    uint32_t a;
    asm("{ .reg .u64 t; cvta.to.shared.u64 t, %1; cvt.u32.u64 %0, t; }"
        : "=r"(a) : "l"(p));
    return a;
}
__device__ __forceinline__ void cp16(uint32_t s, const void* g) {
    asm volatile("cp.async.ca.shared.global [%0], [%1], 16;"
                 :: "r"(s), "l"(g) : "memory");
}
__device__ __forceinline__ void cp_commit() {
    asm volatile("cp.async.commit_group;" ::: "memory");
}
template <int N>
__device__ __forceinline__ void cp_wait() {
    asm volatile("cp.async.wait_group %0;" :: "n"(N) : "memory");
}
__device__ __forceinline__ void split_tf32(float a, uint32_t& hi, uint32_t& lo) {
    uint32_t h;
    asm("cvt.rna.tf32.f32 %0, %1;" : "=r"(h) : "f"(a));
    float r = a - __uint_as_float(h);
    uint32_t l;
    asm("cvt.rna.tf32.f32 %0, %1;" : "=r"(l) : "f"(r));
    hi = h; lo = l;
}
__device__ __forceinline__ void mma8(float* c, const uint32_t* a, const uint32_t* b) {
    asm volatile(
        "mma.sync.aligned.m16n8k8.row.col.f32.tf32.tf32.f32 "
        "{%0,%1,%2,%3}, {%4,%5,%6,%7}, {%8,%9}, {%0,%1,%2,%3};"
        : "+f"(c[0]), "+f"(c[1]), "+f"(c[2]), "+f"(c[3])
        : "r"(a[0]), "r"(a[1]), "r"(a[2]), "r"(a[3]), "r"(b[0]), "r"(b[1]));
}
// ln(1+e^-p) for p in [0,1], no MUFU: ln2 - p/2 + lncosh(p/2) (Taylor, err ~1.5e-8)
__device__ __forceinline__ float softplus_neg01(float p) {
    float x = 0.5f * p;
    float y = x * x;
    float lc = y * (0.5f + y * (-8.3333333333e-2f + y * (2.2222222222e-2f +
               y * (-6.7460317460e-3f + y * (2.1869488536e-3f +
               y * (-7.3860295563e-4f))))));
    return 0.69314718056f - x + lc;
}

// ---------------------------------------------------------------------------
// Transpose + tf32-split all 6 weight matrices:
// g_wT[w][0][n][k] = tf32_hi(W[w][k][n]), g_wT[w][1][n][k] = tf32_lo(...)
// ---------------------------------------------------------------------------
__global__ void transpose6(Ptr6 ws) {
    __shared__ float t[32][33];
    int w = blockIdx.z;
    const float* W = ws.p[w];
    float* Thi = g_wT + (size_t)w * 2 * Dm * Dm;
    float* Tlo = Thi + (size_t)Dm * Dm;
    int n0 = blockIdx.x * 32, k0 = blockIdx.y * 32;
#pragma unroll
    for (int i = 0; i < 4; i++)
        t[threadIdx.y + i * 8][threadIdx.x] =
            W[(size_t)(k0 + threadIdx.y + i * 8) * Dm + n0 + threadIdx.x];
    __syncthreads();
#pragma unroll
    for (int i = 0; i < 4; i++) {
        float v = t[threadIdx.x][threadIdx.y + i * 8];
        uint32_t hi, lo;
        split_tf32(v, hi, lo);
        size_t idx = (size_t)(n0 + threadIdx.y + i * 8) * Dm + k0 + threadIdx.x;
        Thi[idx] = __uint_as_float(hi);
        Tlo[idx] = __uint_as_float(lo);
    }
}

// ---------------------------------------------------------------------------
// mma.sync tf32 GEMM (3x split): C = (A @ W + bias) * scale
// grid (32 m, 12 n, 6 gemms), 256 threads, cp.async double-buffered.
// B hi/lo planes precomputed; A split in-loop.
// ---------------------------------------------------------------------------
__global__ __launch_bounds__(256, 2) void gemm_mma(const float* __restrict__ query,
                                                   const float* __restrict__ key,
                                                   Ptr6 biases)
{
    extern __shared__ char dsm[];
    const int tid = threadIdx.x, warp = tid >> 5, lane = tid & 31;
    const int g = lane >> 2, t = lane & 3;
    const int wm = (warp >> 1) * 32, wn = (warp & 1) * 32;

    const int w = blockIdx.z;
    const float* A  = (w & 1) ? key : query;
    const float* WThi = g_wT + (size_t)w * 2 * Dm * Dm;
    const float* WTlo = WThi + (size_t)Dm * Dm;
    float* C        = g_proj + (size_t)w * Mrows * Dm;
    const float* bias = biases.p[w];
    const float scale = (w & 1) ? 1.0f : SCALE;
    const int m0 = blockIdx.x * BM, n0 = blockIdx.y * BN;

    const uint32_t sb = smem_u32(dsm);

    auto load_stage = [&](int s, int buf) {
        const int kk = s * BK;
        const uint32_t ab = sb + buf * STAGE_B;
        const uint32_t bb = ab + A_BYTES;
#pragma unroll
        for (int i = 0; i < 4; i++) {          // A: 128x32 floats
            int li = i * 256 + tid;
            int row = li >> 3, kq = (li & 7) * 4;
            cp16(ab + (uint32_t)(row * ASTR + kq) * 4,
                 &A[(size_t)(m0 + row) * Dm + kk + kq]);
        }
#pragma unroll
        for (int i = 0; i < 2; i++) {          // B hi: 64x32 floats
            int li = i * 256 + tid;
            int row = li >> 3, kq = (li & 7) * 4;
            cp16(bb + (uint32_t)(row * ASTR + kq) * 4,
                 &WThi[(size_t)(n0 + row) * Dm + kk + kq]);
        }
#pragma unroll
        for (int i = 0; i < 2; i++) {          // B lo: 64x32 floats
            int li = i * 256 + tid;
            int row = li >> 3, kq = (li & 7) * 4;
            cp16(bb + BP_BYTES + (uint32_t)(row * ASTR + kq) * 4,
                 &WTlo[(size_t)(n0 + row) * Dm + kk + kq]);
        }
        cp_commit();
    };

    float acc[2][4][4];
#pragma unroll
    for (int mf = 0; mf < 2; mf++)
#pragma unroll
        for (int nf = 0; nf < 4; nf++)
#pragma unroll
            for (int i = 0; i < 4; i++) acc[mf][nf][i] = 0.0f;

    load_stage(0, 0);

    for (int s = 0; s < NSTAGE; s++) {
        if (s + 1 < NSTAGE) { load_stage(s + 1, (s + 1) & 1); cp_wait<1>(); }
        else                { cp_wait<0>(); }
        __syncthreads();

        const int buf = s & 1;
        const float* As = (const float*)(dsm + buf * STAGE_B);
        const uint32_t* Bh = (const uint32_t*)(dsm + buf * STAGE_B + A_BYTES);
        const uint32_t* Bl = (const uint32_t*)(dsm + buf * STAGE_B + A_BYTES + BP_BYTES);

#pragma unroll
        for (int ks = 0; ks < 4; ks++) {
            const int kq = ks * 8;
            uint32_t ah[2][4], al[2][4], bh[4][2], bl[4][2];
#pragma unroll
            for (int mf = 0; mf < 2; mf++) {
                int r0 = wm + mf * 16 + g;
                split_tf32(As[r0 * ASTR + kq + t],           ah[mf][0], al[mf][0]);
                split_tf32(As[(r0 + 8) * ASTR + kq + t],     ah[mf][1], al[mf][1]);
                split_tf32(As[r0 * ASTR + kq + t + 4],       ah[mf][2], al[mf][2]);
                split_tf32(As[(r0 + 8) * ASTR + kq + t + 4], ah[mf][3], al[mf][3]);
            }
#pragma unroll
            for (int nf = 0; nf < 4; nf++) {
                int n = wn + nf * 8 + g;
                bh[nf][0] = Bh[n * ASTR + kq + t];
                bh[nf][1] = Bh[n * ASTR + kq + t + 4];
                bl[nf][0] = Bl[n * ASTR + kq + t];
                bl[nf][1] = Bl[n * ASTR + kq + t + 4];
            }
#pragma unroll
            for (int mf = 0; mf < 2; mf++)
#pragma unroll
                for (int nf = 0; nf < 4; nf++) {
                    mma8(acc[mf][nf], ah[mf], bh[nf]);
                    mma8(acc[mf][nf], ah[mf], bl[nf]);
                    mma8(acc[mf][nf], al[mf], bh[nf]);
                }
        }
        __syncthreads();
    }

    // Epilogue: c frag rows {g, g+8}, cols {2t, 2t+1} within each m16n8 tile
#pragma unroll
    for (int mf = 0; mf < 2; mf++) {
        int row0 = m0 + wm + mf * 16 + g;
#pragma unroll
        for (int nf = 0; nf < 4; nf++) {
            int col = n0 + wn + nf * 8 + 2 * t;
            float2 bv = *(const float2*)&bias[col];
            float2 o0, o1;
            o0.x = (acc[mf][nf][0] + bv.x) * scale;
            o0.y = (acc[mf][nf][1] + bv.y) * scale;
            o1.x = (acc[mf][nf][2] + bv.x) * scale;
            o1.y = (acc[mf][nf][3] + bv.y) * scale;
            *(float2*)&C[(size_t)row0 * Dm + col]       = o0;
            *(float2*)&C[(size_t)(row0 + 8) * Dm + col] = o1;
        }
    }
}

// ---------------------------------------------------------------------------
// Fused attention: per-(bh, 16-q-row tile) block, 256 threads, 4 q-rows/thread
// (the R3 shape). Softmask in registers; warp-level triangle skip (modes 0/1);
// BCE via MUFU-free softplus polynomial.
// ---------------------------------------------------------------------------
__global__ __launch_bounds__(256) void attn_fused(
    const float* __restrict__ mask,
    const float* __restrict__ span, float* __restrict__ out)
{
    __shared__ float sQ[16][64];
    __shared__ float sKT[16][512];
    __shared__ float sRed[16][2];
    __shared__ float sW[8];

    int tid  = threadIdx.x;
    int lane = tid & 31;
    int half = (tid >> 5) & 1;
    int qg   = tid >> 6;     // 0..3 -> q-group (4 rows each)
    int kg   = tid & 63;     // 0..63 -> 8 consecutive cols each
    int bh = blockIdx.y;
    int b = bh / Hh, h = bh % Hh;
    int q0 = blockIdx.x * 16;

    const int qmin = q0 + qg * 4, qmax = qmin + 3;
    const int c_lo = half * 256, c_hi = c_lo + 255;

    float smk[4][8];     // running soft mask (cumsum products), per-thread

    float rmk[8], rmq[4];
#pragma unroll
    for (int c = 0; c < 8; c++) {
        float mv = mask[b * Sq + kg * 8 + c];
        rmk[c] = (mv == -10000.0f) ? 1.0e9f : mv;
    }
#pragma unroll
    for (int r = 0; r < 4; r++) {
        float mv = mask[b * Sq + qmin + r];
        rmq[r] = (mv == -10000.0f) ? 1.0e9f : mv;
    }

    for (int mode = 0; mode < 3; mode++) {
        const float* Ap = g_proj + (size_t)(mode * 2)     * Mrows * Dm;
        const float* Bp = g_proj + (size_t)(mode * 2 + 1) * Mrows * Dm;

        // warp-uniform: this warp's entire 256-col span is boundary-masked
        const bool skipw = (mode == 0 && c_lo > qmax) ||
                           (mode == 1 && c_hi < qmin);

        __syncthreads();
        {
            int row = tid >> 4;
            int d4  = (tid & 15) * 4;
            *(float4*)&sQ[row][d4] =
                *(const float4*)&Ap[((size_t)(b * Sq + q0 + row)) * Dm + h * Dk + d4];
        }

        float acc[4][8];
#pragma unroll
        for (int r = 0; r < 4; r++)
#pragma unroll
            for (int c = 0; c < 8; c++) acc[r][c] = 0.0f;

        for (int dc = 0; dc < 4; dc++) {
            __syncthreads();
#pragma unroll
            for (int i = 0; i < 8; i++) {
                int lin = i * 256 + tid;
                int tok = lin >> 2;
                int f4  = (lin & 3) * 4;
                float4 v = *(const float4*)&Bp[((size_t)(b * Sq + tok)) * Dm + h * Dk + dc * 16 + f4];
                sKT[f4 + 0][tok] = v.x; sKT[f4 + 1][tok] = v.y;
                sKT[f4 + 2][tok] = v.z; sKT[f4 + 3][tok] = v.w;
            }
            __syncthreads();
            if (skipw) continue;    // scores unused: exp==0, cumsum contribution 0
#pragma unroll
            for (int dd = 0; dd < 16; dd++) {
                float4 k0 = *(const float4*)&sKT[dd][kg * 8];
                float4 k1 = *(const float4*)&sKT[dd][kg * 8 + 4];
#pragma unroll
                for (int r = 0; r < 4; r++) {
                    float qv = sQ[qg * 4 + r][dc * 16 + dd];
                    acc[r][0] += qv * k0.x; acc[r][1] += qv * k0.y;
                    acc[r][2] += qv * k0.z; acc[r][3] += qv * k0.w;
                    acc[r][4] += qv * k1.x; acc[r][5] += qv * k1.y;
                    acc[r][6] += qv * k1.z; acc[r][7] += qv * k1.w;
                }
            }
        }
        __syncthreads();

        // transform + per-row max
#pragma unroll
        for (int r = 0; r < 4; r++) {
            int q = qmin + r;
            float m;
            if (skipw) {
                m = -3.0e38f;
            } else {
                if (mode == 0) {
#pragma unroll
                    for (int c = 0; c < 8; c++)
                        if (kg * 8 + c > q) acc[r][c] -= 1.0e9f;
                } else if (mode == 1) {
#pragma unroll
                    for (int c = 0; c < 8; c++)
                        if (kg * 8 + c < q) acc[r][c] -= 1.0e9f;
                } else {
#pragma unroll
                    for (int c = 0; c < 8; c++)
                        acc[r][c] = (acc[r][c] - rmq[r] - rmk[c]) * smk[r][c];
                }
                m = acc[r][0];
#pragma unroll
                for (int c = 1; c < 8; c++) m = fmaxf(m, acc[r][c]);
#pragma unroll
                for (int off = 16; off >= 1; off >>= 1)
                    m = fmaxf(m, __shfl_xor_sync(0xffffffffu, m, off));
            }
            if (lane == 0) sRed[qg * 4 + r][half] = m;
        }
        __syncthreads();
        float mrow[4];
#pragma unroll
        for (int r = 0; r < 4; r++)
            mrow[r] = fmaxf(sRed[qg * 4 + r][0], sRed[qg * 4 + r][1]);
        __syncthreads();

        if (mode < 2) {
            float tval[4];
#pragma unroll
            for (int r = 0; r < 4; r++) {
                if (skipw) {
#pragma unroll
                    for (int c = 0; c < 8; c++) acc[r][c] = 0.0f;
                    tval[r] = 0.0f;
                    if (lane == 31) sRed[qg * 4 + r][half] = 0.0f;
                } else {
                    float run = 0.0f;
#pragma unroll
                    for (int c = 0; c < 8; c++) {
                        run += __expf(acc[r][c] - mrow[r]);
                        acc[r][c] = run;                 // local inclusive cumsum
                    }
                    float tv = run;
#pragma unroll
                    for (int off = 1; off < 32; off <<= 1) {
                        float u = __shfl_up_sync(0xffffffffu, tv, off);
                        if (lane >= off) tv += u;
                    }
                    tval[r] = tv;                         // inclusive total within warp
                    if (lane == 31) sRed[qg * 4 + r][half] = tv;
                }
            }
            __syncthreads();
#pragma unroll
            for (int r = 0; r < 4; r++) {
                float w0 = sRed[qg * 4 + r][0], w1 = sRed[qg * 4 + r][1];
                float sumrow = w0 + w1;
                float tot = acc[r][7];
                float excl = (half ? w0 : 0.0f) + (tval[r] - tot);
                float inv = 1.0f / sumrow;
                if (mode == 0) {
#pragma unroll
                    for (int c = 0; c < 8; c++)
                        smk[r][c] = (excl + acc[r][c]) * inv;
                } else {
                    // rev_incl[c] = sumrow - excl - local_incl[c-1]
                    float base = sumrow - excl;
                    smk[r][0] *= base * inv;
#pragma unroll
                    for (int c = 1; c < 8; c++)
                        smk[r][c] *= (base - acc[r][c - 1]) * inv;
                }
            }
        } else {
            float lsum = 0.0f;
#pragma unroll
            for (int r = 0; r < 4; r++) {
                float s = 0.0f;
#pragma unroll
                for (int c = 0; c < 8; c++) {
                    acc[r][c] = __expf(acc[r][c] - mrow[r]);
                    s += acc[r][c];
                }
#pragma unroll
                for (int off = 16; off >= 1; off >>= 1)
                    s += __shfl_xor_sync(0xffffffffu, s, off);
                if (lane == 0) sRed[qg * 4 + r][half] = s;
            }
            __syncthreads();
#pragma unroll
            for (int r = 0; r < 4; r++) {
                int q = qmin + r;
                float inv = 1.0f / (sRed[qg * 4 + r][0] + sRed[qg * 4 + r][1]);
                size_t oidx = ((size_t)bh * Sq + q) * Sq + kg * 8;
                size_t sidx = ((size_t)((h * Bq + b) * Sq + q)) * Sq + kg * 8;
                float4 sp0 = *(const float4*)&span[sidx];
                float4 sp1 = *(const float4*)&span[sidx + 4];
                float sp[8] = {sp0.x, sp0.y, sp0.z, sp0.w, sp1.x, sp1.y, sp1.z, sp1.w};
                float p[8];
#pragma unroll
                for (int c = 0; c < 8; c++) p[c] = acc[r][c] * inv;
                float4 o0 = {p[0], p[1], p[2], p[3]};
                float4 o1 = {p[4], p[5], p[6], p[7]};
                *(float4*)&out[oidx]     = o0;
                *(float4*)&out[oidx + 4] = o1;
                // bce = ln(1+e^-p) + p*(1-span)   (MUFU-free softplus)
#pragma unroll
                for (int c = 0; c < 8; c++)
                    lsum += softplus_neg01(p[c]) + p[c] * (1.0f - sp[c]);
            }
#pragma unroll
            for (int off = 16; off >= 1; off >>= 1)
                lsum += __shfl_xor_sync(0xffffffffu, lsum, off);
            __syncthreads();
            if (lane == 0) sW[tid >> 5] = lsum;
            __syncthreads();
            if (tid == 0) {
                float tot = 0.0f;
#pragma unroll
                for (int ww = 0; ww < 8; ww++) tot += sW[ww];
                atomicAdd(&g_loss, (double)tot);
            }
        }
    }
}

__global__ void zero_loss_kernel() { g_loss = 0.0; }

__global__ void finalize_kernel(float* out, int out_size) {
    if (out_size > NATT)
        out[NATT] = (float)(g_loss / (double)NATT);
}

// ---------------------------------------------------------------------------
extern "C" void kernel_launch(void* const* d_in, const int* in_sizes, int n_in,
                              void* d_out, int out_size)
{
    (void)in_sizes; (void)n_in;
    const float* query = (const float*)d_in[0];
    const float* key   = (const float*)d_in[1];
    const float* mask  = (const float*)d_in[2];
    const float* span  = (const float*)d_in[3];
    float* out = (float*)d_out;

    Ptr6 ws, bs;
    for (int w = 0; w < 6; w++) {
        ws.p[w] = (const float*)d_in[4 + 2 * w];
        bs.p[w] = (const float*)d_in[5 + 2 * w];
    }

    cudaFuncSetAttribute(gemm_mma, cudaFuncAttributeMaxDynamicSharedMemorySize, DYN_SMEM);

    transpose6<<<dim3(Dm / 32, Dm / 32, 6), dim3(32, 8)>>>(ws);
    gemm_mma<<<dim3(Mrows / BM, Dm / BN, 6), 256, DYN_SMEM>>>(query, key, bs);
    zero_loss_kernel<<<1, 1>>>();
    attn_fused<<<dim3(Sq / 16, BHn), 256>>>(mask, span, out);
    finalize_kernel<<<1, 1>>>(out, out_size);
}

// round 7
// speedup vs baseline: 1.2581x; 1.0885x over previous
#include <cuda_runtime.h>
#include <cstdint>
#include <math.h>

#define Bq    8
#define Sq    512
#define Dm    768
#define Hh    12
#define Dk    64
#define BHn   (Bq*Hh)            // 96
#define Mrows (Bq*Sq)            // 4096
#define NATT  (25165824)         // B*H*S*S
#define SCALE 0.036084391824351615f   // 1/sqrt(768)

// ---- projection GEMM tiling ----
#define BM 128
#define BN 64
#define BK 32
#define ASTR 36                        // padded k-stride (floats), conflict-free
#define A_BYTES (BM*ASTR*4)            // 18432
#define BP_BYTES (BN*ASTR*4)           // 9216 per plane
#define B_BYTES (2*BP_BYTES)           // 18432 (hi+lo planes)
#define STAGE_B (A_BYTES + B_BYTES)    // 36864
#define DYN_SMEM (2*STAGE_B)           // 73728
#define NSTAGE (Dm/BK)                 // 24

// ---- attn smem layout (floats) ----
#define SQ_STR   68
#define SKB_STR  20
#define SS_STR   520
#define OFF_SQ   0
#define OFF_SKB  (16*SQ_STR)                  // 1088
#define OFF_SS   (OFF_SKB + 512*SKB_STR)      // 11328
#define OFF_RED  (OFF_SS + 16*SS_STR)         // 19648
#define OFF_W    (OFF_RED + 32)               // 19680
#define ATTN_SMEM_FLOATS (OFF_W + 8)          // 19688
#define ATTN_SMEM_BYTES  (ATTN_SMEM_FLOATS*4) // 78752

// Scratch (device globals: allocation-free, graph-capturable)
__device__ float  g_proj[(size_t)6 * Mrows * Dm];     // ql,kl,qr,kr,q,k
__device__ float  g_wT[(size_t)6 * 2 * Dm * Dm];      // per w: hi plane, lo plane (n-major)
__device__ double g_loss;

struct Ptr6 { const float* p[6]; };

// ---------------------------------------------------------------------------
// helpers
// ---------------------------------------------------------------------------
__device__ __forceinline__ uint32_t smem_u32(const void* p) {
    uint32_t a;
    asm("{ .reg .u64 t; cvta.to.shared.u64 t, %1; cvt.u32.u64 %0, t; }"
        : "=r"(a) : "l"(p));
    return a;
}
__device__ __forceinline__ void cp16(uint32_t s, const void* g) {
    asm volatile("cp.async.ca.shared.global [%0], [%1], 16;"
                 :: "r"(s), "l"(g) : "memory");
}
__device__ __forceinline__ void cp_commit() {
    asm volatile("cp.async.commit_group;" ::: "memory");
}
template <int N>
__device__ __forceinline__ void cp_wait() {
    asm volatile("cp.async.wait_group %0;" :: "n"(N) : "memory");
}
__device__ __forceinline__ void split_tf32(float a, uint32_t& hi, uint32_t& lo) {
    uint32_t h;
    asm("cvt.rna.tf32.f32 %0, %1;" : "=r"(h) : "f"(a));
    float r = a - __uint_as_float(h);
    uint32_t l;
    asm("cvt.rna.tf32.f32 %0, %1;" : "=r"(l) : "f"(r));
    hi = h; lo = l;
}
__device__ __forceinline__ void mma8(float* c, const uint32_t* a, const uint32_t* b) {
    asm volatile(
        "mma.sync.aligned.m16n8k8.row.col.f32.tf32.tf32.f32 "
        "{%0,%1,%2,%3}, {%4,%5,%6,%7}, {%8,%9}, {%0,%1,%2,%3};"
        : "+f"(c[0]), "+f"(c[1]), "+f"(c[2]), "+f"(c[3])
        : "r"(a[0]), "r"(a[1]), "r"(a[2]), "r"(a[3]), "r"(b[0]), "r"(b[1]));
}
// ln(1+e^-p) for p in [0,1], no MUFU: ln2 - p/2 + lncosh(p/2) (Taylor, err ~1.5e-8)
__device__ __forceinline__ float softplus_neg01(float p) {
    float x = 0.5f * p;
    float y = x * x;
    float lc = y * (0.5f + y * (-8.3333333333e-2f + y * (2.2222222222e-2f +
               y * (-6.7460317460e-3f + y * (2.1869488536e-3f +
               y * (-7.3860295563e-4f))))));
    return 0.69314718056f - x + lc;
}

// ---------------------------------------------------------------------------
// Transpose + tf32-split all 6 weight matrices:
// g_wT[w][0][n][k] = tf32_hi(W[w][k][n]), g_wT[w][1][n][k] = tf32_lo(...)
// ---------------------------------------------------------------------------
__global__ void transpose6(Ptr6 ws) {
    __shared__ float t[32][33];
    int w = blockIdx.z;
    const float* W = ws.p[w];
    float* Thi = g_wT + (size_t)w * 2 * Dm * Dm;
    float* Tlo = Thi + (size_t)Dm * Dm;
    int n0 = blockIdx.x * 32, k0 = blockIdx.y * 32;
#pragma unroll
    for (int i = 0; i < 4; i++)
        t[threadIdx.y + i * 8][threadIdx.x] =
            W[(size_t)(k0 + threadIdx.y + i * 8) * Dm + n0 + threadIdx.x];
    __syncthreads();
#pragma unroll
    for (int i = 0; i < 4; i++) {
        float v = t[threadIdx.x][threadIdx.y + i * 8];
        uint32_t hi, lo;
        split_tf32(v, hi, lo);
        size_t idx = (size_t)(n0 + threadIdx.y + i * 8) * Dm + k0 + threadIdx.x;
        Thi[idx] = __uint_as_float(hi);
        Tlo[idx] = __uint_as_float(lo);
    }
}

// ---------------------------------------------------------------------------
// mma.sync tf32 GEMM (3x split): C = (A @ W + bias) * scale
// grid (32 m, 12 n, 6 gemms), 256 threads, cp.async double-buffered.
// ---------------------------------------------------------------------------
__global__ __launch_bounds__(256, 2) void gemm_mma(const float* __restrict__ query,
                                                   const float* __restrict__ key,
                                                   Ptr6 biases)
{
    extern __shared__ char dsm[];
    const int tid = threadIdx.x, warp = tid >> 5, lane = tid & 31;
    const int g = lane >> 2, t = lane & 3;
    const int wm = (warp >> 1) * 32, wn = (warp & 1) * 32;

    const int w = blockIdx.z;
    const float* A  = (w & 1) ? key : query;
    const float* WThi = g_wT + (size_t)w * 2 * Dm * Dm;
    const float* WTlo = WThi + (size_t)Dm * Dm;
    float* C        = g_proj + (size_t)w * Mrows * Dm;
    const float* bias = biases.p[w];
    const float scale = (w & 1) ? 1.0f : SCALE;
    const int m0 = blockIdx.x * BM, n0 = blockIdx.y * BN;

    const uint32_t sb = smem_u32(dsm);

    auto load_stage = [&](int s, int buf) {
        const int kk = s * BK;
        const uint32_t ab = sb + buf * STAGE_B;
        const uint32_t bb = ab + A_BYTES;
#pragma unroll
        for (int i = 0; i < 4; i++) {          // A: 128x32 floats
            int li = i * 256 + tid;
            int row = li >> 3, kq = (li & 7) * 4;
            cp16(ab + (uint32_t)(row * ASTR + kq) * 4,
                 &A[(size_t)(m0 + row) * Dm + kk + kq]);
        }
#pragma unroll
        for (int i = 0; i < 2; i++) {          // B hi
            int li = i * 256 + tid;
            int row = li >> 3, kq = (li & 7) * 4;
            cp16(bb + (uint32_t)(row * ASTR + kq) * 4,
                 &WThi[(size_t)(n0 + row) * Dm + kk + kq]);
        }
#pragma unroll
        for (int i = 0; i < 2; i++) {          // B lo
            int li = i * 256 + tid;
            int row = li >> 3, kq = (li & 7) * 4;
            cp16(bb + BP_BYTES + (uint32_t)(row * ASTR + kq) * 4,
                 &WTlo[(size_t)(n0 + row) * Dm + kk + kq]);
        }
        cp_commit();
    };

    float acc[2][4][4];
#pragma unroll
    for (int mf = 0; mf < 2; mf++)
#pragma unroll
        for (int nf = 0; nf < 4; nf++)
#pragma unroll
            for (int i = 0; i < 4; i++) acc[mf][nf][i] = 0.0f;

    load_stage(0, 0);

    for (int s = 0; s < NSTAGE; s++) {
        if (s + 1 < NSTAGE) { load_stage(s + 1, (s + 1) & 1); cp_wait<1>(); }
        else                { cp_wait<0>(); }
        __syncthreads();

        const int buf = s & 1;
        const float* As = (const float*)(dsm + buf * STAGE_B);
        const uint32_t* Bh = (const uint32_t*)(dsm + buf * STAGE_B + A_BYTES);
        const uint32_t* Bl = (const uint32_t*)(dsm + buf * STAGE_B + A_BYTES + BP_BYTES);

#pragma unroll
        for (int ks = 0; ks < 4; ks++) {
            const int kq = ks * 8;
            uint32_t ah[2][4], al[2][4], bh[4][2], bl[4][2];
#pragma unroll
            for (int mf = 0; mf < 2; mf++) {
                int r0 = wm + mf * 16 + g;
                split_tf32(As[r0 * ASTR + kq + t],           ah[mf][0], al[mf][0]);
                split_tf32(As[(r0 + 8) * ASTR + kq + t],     ah[mf][1], al[mf][1]);
                split_tf32(As[r0 * ASTR + kq + t + 4],       ah[mf][2], al[mf][2]);
                split_tf32(As[(r0 + 8) * ASTR + kq + t + 4], ah[mf][3], al[mf][3]);
            }
#pragma unroll
            for (int nf = 0; nf < 4; nf++) {
                int n = wn + nf * 8 + g;
                bh[nf][0] = Bh[n * ASTR + kq + t];
                bh[nf][1] = Bh[n * ASTR + kq + t + 4];
                bl[nf][0] = Bl[n * ASTR + kq + t];
                bl[nf][1] = Bl[n * ASTR + kq + t + 4];
            }
#pragma unroll
            for (int mf = 0; mf < 2; mf++)
#pragma unroll
                for (int nf = 0; nf < 4; nf++) {
                    mma8(acc[mf][nf], ah[mf], bh[nf]);
                    mma8(acc[mf][nf], ah[mf], bl[nf]);
                    mma8(acc[mf][nf], al[mf], bh[nf]);
                }
        }
        __syncthreads();
    }

#pragma unroll
    for (int mf = 0; mf < 2; mf++) {
        int row0 = m0 + wm + mf * 16 + g;
#pragma unroll
        for (int nf = 0; nf < 4; nf++) {
            int col = n0 + wn + nf * 8 + 2 * t;
            float2 bv = *(const float2*)&bias[col];
            float2 o0, o1;
            o0.x = (acc[mf][nf][0] + bv.x) * scale;
            o0.y = (acc[mf][nf][1] + bv.y) * scale;
            o1.x = (acc[mf][nf][2] + bv.x) * scale;
            o1.y = (acc[mf][nf][3] + bv.y) * scale;
            *(float2*)&C[(size_t)row0 * Dm + col]       = o0;
            *(float2*)&C[(size_t)(row0 + 8) * Dm + col] = o1;
        }
    }
}

// ---------------------------------------------------------------------------
// Fused attention with tensor-core score GEMMs.
// Block = (bh, 16 q-rows), 256 threads.
// Producer: 8 warps, each computes m16 x n64 score tile via mma.sync tf32
//           (3x split), K staged per 16-d chunk in [n][k] smem.
// Scores -> smem tile -> consumer phase (identical to validated R5 logic).
// ---------------------------------------------------------------------------
__global__ __launch_bounds__(256) void attn_fused(
    const float* __restrict__ mask,
    const float* __restrict__ span, float* __restrict__ out)
{
    extern __shared__ float smf[];
    float* sQ  = smf + OFF_SQ;    // [16][68]
    float* sKB = smf + OFF_SKB;   // [512][20]
    float* sS  = smf + OFF_SS;    // [16][520]
    float* sRed= smf + OFF_RED;   // [16][2]
    float* sW  = smf + OFF_W;     // [8]

    int tid  = threadIdx.x;
    int lane = tid & 31;
    int warp = tid >> 5;        // 0..7
    int g    = lane >> 2, t = lane & 3;
    int wn   = warp * 64;       // producer col base
    int half = (tid >> 5) & 1;  // consumer: which 256-col half
    int qg   = tid >> 6;        // consumer: 0..3 -> q-group (4 rows each)
    int kg   = tid & 63;        // consumer: 0..63 -> 8 consecutive cols each
    int bh = blockIdx.y;
    int b = bh / Hh, h = bh % Hh;
    int q0 = blockIdx.x * 16;

    const int qmin = q0 + qg * 4, qmax = qmin + 3;
    const int c_lo = half * 256, c_hi = c_lo + 255;

    float smk[4][8];     // running soft mask (cumsum products), per consumer thread

    float rmk[8], rmq[4];
#pragma unroll
    for (int c = 0; c < 8; c++) {
        float mv = mask[b * Sq + kg * 8 + c];
        rmk[c] = (mv == -10000.0f) ? 1.0e9f : mv;
    }
#pragma unroll
    for (int r = 0; r < 4; r++) {
        float mv = mask[b * Sq + qmin + r];
        rmq[r] = (mv == -10000.0f) ? 1.0e9f : mv;
    }

    for (int mode = 0; mode < 3; mode++) {
        const float* Ap = g_proj + (size_t)(mode * 2)     * Mrows * Dm;
        const float* Bp = g_proj + (size_t)(mode * 2 + 1) * Mrows * Dm;

        // producer skip: warp's entire 64-col span boundary-masked (modes 0/1)
        const bool skipp = (mode == 0 && wn > q0 + 15) ||
                           (mode == 1 && wn + 63 < q0);
        // consumer skip: thread's 256-col half fully masked for its 4 rows
        const bool skipc = (mode == 0 && c_lo > qmax) ||
                           (mode == 1 && c_hi < qmin);

        __syncthreads();
        {   // stage Q tile 16x64
            int row = tid >> 4;
            int d4  = (tid & 15) * 4;
            *(float4*)&sQ[row * SQ_STR + d4] =
                *(const float4*)&Ap[((size_t)(b * Sq + q0 + row)) * Dm + h * Dk + d4];
        }

        float accp[8][4];
#pragma unroll
        for (int nf = 0; nf < 8; nf++)
#pragma unroll
            for (int i = 0; i < 4; i++) accp[nf][i] = 0.0f;

        for (int dc = 0; dc < 4; dc++) {
            __syncthreads();
            // stage K chunk: [512 tokens][16 d] at stride 20
#pragma unroll
            for (int i = 0; i < 8; i++) {
                int lin = i * 256 + tid;
                int tok = lin >> 2;
                int f4  = (lin & 3) * 4;
                *(float4*)&sKB[tok * SKB_STR + f4] =
                    *(const float4*)&Bp[((size_t)(b * Sq + tok)) * Dm + h * Dk + dc * 16 + f4];
            }
            __syncthreads();
            if (skipp) continue;
#pragma unroll
            for (int ks = 0; ks < 2; ks++) {
                const int kqg = dc * 16 + ks * 8;   // global d for Q
                const int kc  = ks * 8;             // within-chunk d for K
                uint32_t ah[4], al[4];
                split_tf32(sQ[g * SQ_STR + kqg + t],           ah[0], al[0]);
                split_tf32(sQ[(g + 8) * SQ_STR + kqg + t],     ah[1], al[1]);
                split_tf32(sQ[g * SQ_STR + kqg + t + 4],       ah[2], al[2]);
                split_tf32(sQ[(g + 8) * SQ_STR + kqg + t + 4], ah[3], al[3]);
#pragma unroll
                for (int nf = 0; nf < 8; nf++) {
                    int n = wn + nf * 8 + g;        // FIX: warp column offset
                    uint32_t bh[2], bl[2];
                    split_tf32(sKB[n * SKB_STR + kc + t],     bh[0], bl[0]);
                    split_tf32(sKB[n * SKB_STR + kc + t + 4], bh[1], bl[1]);
                    mma8(accp[nf], ah, bh);
                    mma8(accp[nf], ah, bl);
                    mma8(accp[nf], al, bh);
                }
            }
        }
        // store scores (skipped warps store zeros)
#pragma unroll
        for (int nf = 0; nf < 8; nf++) {
            int col = wn + nf * 8 + 2 * t;
            *(float2*)&sS[g * SS_STR + col]       = make_float2(accp[nf][0], accp[nf][1]);
            *(float2*)&sS[(g + 8) * SS_STR + col] = make_float2(accp[nf][2], accp[nf][3]);
        }
        __syncthreads();

        // ---------------- consumer phase (validated R5 logic) ----------------
        float acc[4][8];
        if (!skipc) {
#pragma unroll
            for (int r = 0; r < 4; r++) {
                const float* srow = &sS[(qg * 4 + r) * SS_STR + kg * 8];
                float4 s0 = *(const float4*)&srow[0];
                float4 s1 = *(const float4*)&srow[4];
                acc[r][0] = s0.x; acc[r][1] = s0.y; acc[r][2] = s0.z; acc[r][3] = s0.w;
                acc[r][4] = s1.x; acc[r][5] = s1.y; acc[r][6] = s1.z; acc[r][7] = s1.w;
            }
        }

        // transform + per-row max
#pragma unroll
        for (int r = 0; r < 4; r++) {
            int q = qmin + r;
            float m;
            if (skipc) {
                m = -3.0e38f;
            } else {
                if (mode == 0) {
#pragma unroll
                    for (int c = 0; c < 8; c++)
                        if (kg * 8 + c > q) acc[r][c] -= 1.0e9f;
                } else if (mode == 1) {
#pragma unroll
                    for (int c = 0; c < 8; c++)
                        if (kg * 8 + c < q) acc[r][c] -= 1.0e9f;
                } else {
#pragma unroll
                    for (int c = 0; c < 8; c++)
                        acc[r][c] = (acc[r][c] - rmq[r] - rmk[c]) * smk[r][c];
                }
                m = acc[r][0];
#pragma unroll
                for (int c = 1; c < 8; c++) m = fmaxf(m, acc[r][c]);
#pragma unroll
                for (int off = 16; off >= 1; off >>= 1)
                    m = fmaxf(m, __shfl_xor_sync(0xffffffffu, m, off));
            }
            if (lane == 0) sRed[(qg * 4 + r) * 2 + half] = m;
        }
        __syncthreads();
        float mrow[4];
#pragma unroll
        for (int r = 0; r < 4; r++)
            mrow[r] = fmaxf(sRed[(qg * 4 + r) * 2 + 0], sRed[(qg * 4 + r) * 2 + 1]);
        __syncthreads();

        if (mode < 2) {
            float tval[4];
#pragma unroll
            for (int r = 0; r < 4; r++) {
                if (skipc) {
#pragma unroll
                    for (int c = 0; c < 8; c++) acc[r][c] = 0.0f;
                    tval[r] = 0.0f;
                    if (lane == 31) sRed[(qg * 4 + r) * 2 + half] = 0.0f;
                } else {
                    float run = 0.0f;
#pragma unroll
                    for (int c = 0; c < 8; c++) {
                        run += __expf(acc[r][c] - mrow[r]);
                        acc[r][c] = run;                 // local inclusive cumsum
                    }
                    float tv = run;
#pragma unroll
                    for (int off = 1; off < 32; off <<= 1) {
                        float u = __shfl_up_sync(0xffffffffu, tv, off);
                        if (lane >= off) tv += u;
                    }
                    tval[r] = tv;
                    if (lane == 31) sRed[(qg * 4 + r) * 2 + half] = tv;
                }
            }
            __syncthreads();
#pragma unroll
            for (int r = 0; r < 4; r++) {
                float w0 = sRed[(qg * 4 + r) * 2 + 0], w1 = sRed[(qg * 4 + r) * 2 + 1];
                float sumrow = w0 + w1;
                float tot = acc[r][7];
                float excl = (half ? w0 : 0.0f) + (tval[r] - tot);
                float inv = 1.0f / sumrow;
                if (mode == 0) {
#pragma unroll
                    for (int c = 0; c < 8; c++)
                        smk[r][c] = (excl + acc[r][c]) * inv;
                } else {
                    float base = sumrow - excl;
                    smk[r][0] *= base * inv;
#pragma unroll
                    for (int c = 1; c < 8; c++)
                        smk[r][c] *= (base - acc[r][c - 1]) * inv;
                }
            }
        } else {
            float lsum = 0.0f;
#pragma unroll
            for (int r = 0; r < 4; r++) {
                float s = 0.0f;
#pragma unroll
                for (int c = 0; c < 8; c++) {
                    acc[r][c] = __expf(acc[r][c] - mrow[r]);
                    s += acc[r][c];
                }
#pragma unroll
                for (int off = 16; off >= 1; off >>= 1)
                    s += __shfl_xor_sync(0xffffffffu, s, off);
                if (lane == 0) sRed[(qg * 4 + r) * 2 + half] = s;
            }
            __syncthreads();
#pragma unroll
            for (int r = 0; r < 4; r++) {
                int q = qmin + r;
                float inv = 1.0f / (sRed[(qg * 4 + r) * 2 + 0] + sRed[(qg * 4 + r) * 2 + 1]);
                size_t oidx = ((size_t)bh * Sq + q) * Sq + kg * 8;
                size_t sidx = ((size_t)((h * Bq + b) * Sq + q)) * Sq + kg * 8;
                float4 sp0 = *(const float4*)&span[sidx];
                float4 sp1 = *(const float4*)&span[sidx + 4];
                float sp[8] = {sp0.x, sp0.y, sp0.z, sp0.w, sp1.x, sp1.y, sp1.z, sp1.w};
                float p[8];
#pragma unroll
                for (int c = 0; c < 8; c++) p[c] = acc[r][c] * inv;
                float4 o0 = {p[0], p[1], p[2], p[3]};
                float4 o1 = {p[4], p[5], p[6], p[7]};
                *(float4*)&out[oidx]     = o0;
                *(float4*)&out[oidx + 4] = o1;
#pragma unroll
                for (int c = 0; c < 8; c++)
                    lsum += softplus_neg01(p[c]) + p[c] * (1.0f - sp[c]);
            }
#pragma unroll
            for (int off = 16; off >= 1; off >>= 1)
                lsum += __shfl_xor_sync(0xffffffffu, lsum, off);
            __syncthreads();
            if (lane == 0) sW[warp] = lsum;
            __syncthreads();
            if (tid == 0) {
                float tot = 0.0f;
#pragma unroll
                for (int ww = 0; ww < 8; ww++) tot += sW[ww];
                atomicAdd(&g_loss, (double)tot);
            }
        }
    }
}

__global__ void zero_loss_kernel() { g_loss = 0.0; }

__global__ void finalize_kernel(float* out, int out_size) {
    if (out_size > NATT)
        out[NATT] = (float)(g_loss / (double)NATT);
}

// ---------------------------------------------------------------------------
extern "C" void kernel_launch(void* const* d_in, const int* in_sizes, int n_in,
                              void* d_out, int out_size)
{
    (void)in_sizes; (void)n_in;
    const float* query = (const float*)d_in[0];
    const float* key   = (const float*)d_in[1];
    const float* mask  = (const float*)d_in[2];
    const float* span  = (const float*)d_in[3];
    float* out = (float*)d_out;

    Ptr6 ws, bs;
    for (int w = 0; w < 6; w++) {
        ws.p[w] = (const float*)d_in[4 + 2 * w];
        bs.p[w] = (const float*)d_in[5 + 2 * w];
    }

    cudaFuncSetAttribute(gemm_mma, cudaFuncAttributeMaxDynamicSharedMemorySize, DYN_SMEM);
    cudaFuncSetAttribute(attn_fused, cudaFuncAttributeMaxDynamicSharedMemorySize, ATTN_SMEM_BYTES);

    transpose6<<<dim3(Dm / 32, Dm / 32, 6), dim3(32, 8)>>>(ws);
    gemm_mma<<<dim3(Mrows / BM, Dm / BN, 6), 256, DYN_SMEM>>>(query, key, bs);
    zero_loss_kernel<<<1, 1>>>();
    attn_fused<<<dim3(Sq / 16, BHn), 256, ATTN_SMEM_BYTES>>>(mask, span, out);
    finalize_kernel<<<1, 1>>>(out, out_size);
}

// round 9
// speedup vs baseline: 1.4924x; 1.1863x over previous
#include <cuda_runtime.h>
#include <cstdint>
#include <math.h>

#define Bq    8
#define Sq    512
#define Dm    768
#define Hh    12
#define Dk    64
#define BHn   (Bq*Hh)            // 96
#define Mrows (Bq*Sq)            // 4096
#define NATT  (25165824)         // B*H*S*S
#define SCALE 0.036084391824351615f   // 1/sqrt(768)

// ---- projection GEMM tiling ----
#define BM 128
#define BN 64
#define BK 32
#define ASTR 36                        // padded k-stride (floats), conflict-free
#define A_BYTES (BM*ASTR*4)            // 18432
#define BP_BYTES (BN*ASTR*4)           // 9216 per plane
#define B_BYTES (2*BP_BYTES)           // 18432 (hi+lo planes)
#define STAGE_B (A_BYTES + B_BYTES)    // 36864
#define DYN_SMEM (2*STAGE_B)           // 73728
#define NSTAGE (Dm/BK)                 // 24

// ---- attn smem layout (floats) ----
#define SQ_STR   68
#define SKB_STR  20
#define SS_STR   520
#define OFF_SQ   0
#define OFF_SKB  (16*SQ_STR)                  // 1088
#define OFF_SS   (OFF_SKB + 512*SKB_STR)      // 11328
#define OFF_RED  (OFF_SS + 16*SS_STR)         // 19648
#define OFF_W    (OFF_RED + 32)               // 19680
#define ATTN_SMEM_FLOATS (OFF_W + 8)          // 19688
#define ATTN_SMEM_BYTES  (ATTN_SMEM_FLOATS*4) // 78752

// Scratch (device globals: allocation-free, graph-capturable)
__device__ float  g_proj[(size_t)6 * Mrows * Dm];     // ql,kl,qr,kr,q,k
__device__ float  g_wT[(size_t)6 * 2 * Dm * Dm];      // per w: hi plane, lo plane (n-major)
__device__ double g_loss;

struct Ptr6 { const float* p[6]; };

// ---------------------------------------------------------------------------
// helpers
// ---------------------------------------------------------------------------
__device__ __forceinline__ uint32_t smem_u32(const void* p) {
    uint32_t a;
    asm("{ .reg .u64 t; cvta.to.shared.u64 t, %1; cvt.u32.u64 %0, t; }"
        : "=r"(a) : "l"(p));
    return a;
}
__device__ __forceinline__ void cp16(uint32_t s, const void* g) {
    asm volatile("cp.async.ca.shared.global [%0], [%1], 16;"
                 :: "r"(s), "l"(g) : "memory");
}
__device__ __forceinline__ void cp_commit() {
    asm volatile("cp.async.commit_group;" ::: "memory");
}
template <int N>
__device__ __forceinline__ void cp_wait() {
    asm volatile("cp.async.wait_group %0;" :: "n"(N) : "memory");
}
// Bitwise tf32 split: hi = truncate-to-tf32(a) (exact in tf32), lo = a - hi
// (exact), lo truncated to tf32 bits. ALU-only (LOP3/FADD), no slow cvt.
__device__ __forceinline__ void split_bits(float a, uint32_t& hi, uint32_t& lo) {
    uint32_t h = __float_as_uint(a) & 0xFFFFE000u;
    float lf = a - __uint_as_float(h);
    hi = h;
    lo = __float_as_uint(lf) & 0xFFFFE000u;
}
__device__ __forceinline__ void mma8(float* c, const uint32_t* a, const uint32_t* b) {
    asm volatile(
        "mma.sync.aligned.m16n8k8.row.col.f32.tf32.tf32.f32 "
        "{%0,%1,%2,%3}, {%4,%5,%6,%7}, {%8,%9}, {%0,%1,%2,%3};"
        : "+f"(c[0]), "+f"(c[1]), "+f"(c[2]), "+f"(c[3])
        : "r"(a[0]), "r"(a[1]), "r"(a[2]), "r"(a[3]), "r"(b[0]), "r"(b[1]));
}
// ln(1+e^-p) for p in [0,1], no MUFU: ln2 - p/2 + lncosh(p/2) (Taylor, err ~1.5e-8)
__device__ __forceinline__ float softplus_neg01(float p) {
    float x = 0.5f * p;
    float y = x * x;
    float lc = y * (0.5f + y * (-8.3333333333e-2f + y * (2.2222222222e-2f +
               y * (-6.7460317460e-3f + y * (2.1869488536e-3f +
               y * (-7.3860295563e-4f))))));
    return 0.69314718056f - x + lc;
}

// ---------------------------------------------------------------------------
// Transpose + tf32-split all 6 weight matrices:
// g_wT[w][0][n][k] = tf32_hi(W[w][k][n]), g_wT[w][1][n][k] = tf32_lo(...)
// ---------------------------------------------------------------------------
__global__ void transpose6(Ptr6 ws) {
    __shared__ float t[32][33];
    int w = blockIdx.z;
    const float* W = ws.p[w];
    float* Thi = g_wT + (size_t)w * 2 * Dm * Dm;
    float* Tlo = Thi + (size_t)Dm * Dm;
    int n0 = blockIdx.x * 32, k0 = blockIdx.y * 32;
#pragma unroll
    for (int i = 0; i < 4; i++)
        t[threadIdx.y + i * 8][threadIdx.x] =
            W[(size_t)(k0 + threadIdx.y + i * 8) * Dm + n0 + threadIdx.x];
    __syncthreads();
#pragma unroll
    for (int i = 0; i < 4; i++) {
        float v = t[threadIdx.x][threadIdx.y + i * 8];
        uint32_t hi, lo;
        split_bits(v, hi, lo);
        size_t idx = (size_t)(n0 + threadIdx.y + i * 8) * Dm + k0 + threadIdx.x;
        Thi[idx] = __uint_as_float(hi);
        Tlo[idx] = __uint_as_float(lo);
    }
}

// ---------------------------------------------------------------------------
// mma.sync tf32 GEMM (3x split): C = (A @ W + bias) * scale
// grid (32 m, 12 n, 6 gemms), 256 threads, cp.async double-buffered.
// ---------------------------------------------------------------------------
__global__ __launch_bounds__(256, 2) void gemm_mma(const float* __restrict__ query,
                                                   const float* __restrict__ key,
                                                   Ptr6 biases)
{
    extern __shared__ char dsm[];
    const int tid = threadIdx.x, warp = tid >> 5, lane = tid & 31;
    const int g = lane >> 2, t = lane & 3;
    const int wm = (warp >> 1) * 32, wn = (warp & 1) * 32;

    const int w = blockIdx.z;
    const float* A  = (w & 1) ? key : query;
    const float* WThi = g_wT + (size_t)w * 2 * Dm * Dm;
    const float* WTlo = WThi + (size_t)Dm * Dm;
    float* C        = g_proj + (size_t)w * Mrows * Dm;
    const float* bias = biases.p[w];
    const float scale = (w & 1) ? 1.0f : SCALE;
    const int m0 = blockIdx.x * BM, n0 = blockIdx.y * BN;

    const uint32_t sb = smem_u32(dsm);

    auto load_stage = [&](int s, int buf) {
        const int kk = s * BK;
        const uint32_t ab = sb + buf * STAGE_B;
        const uint32_t bb = ab + A_BYTES;
#pragma unroll
        for (int i = 0; i < 4; i++) {          // A: 128x32 floats
            int li = i * 256 + tid;
            int row = li >> 3, kq = (li & 7) * 4;
            cp16(ab + (uint32_t)(row * ASTR + kq) * 4,
                 &A[(size_t)(m0 + row) * Dm + kk + kq]);
        }
#pragma unroll
        for (int i = 0; i < 2; i++) {          // B hi
            int li = i * 256 + tid;
            int row = li >> 3, kq = (li & 7) * 4;
            cp16(bb + (uint32_t)(row * ASTR + kq) * 4,
                 &WThi[(size_t)(n0 + row) * Dm + kk + kq]);
        }
#pragma unroll
        for (int i = 0; i < 2; i++) {          // B lo
            int li = i * 256 + tid;
            int row = li >> 3, kq = (li & 7) * 4;
            cp16(bb + BP_BYTES + (uint32_t)(row * ASTR + kq) * 4,
                 &WTlo[(size_t)(n0 + row) * Dm + kk + kq]);
        }
        cp_commit();
    };

    float acc[2][4][4];
#pragma unroll
    for (int mf = 0; mf < 2; mf++)
#pragma unroll
        for (int nf = 0; nf < 4; nf++)
#pragma unroll
            for (int i = 0; i < 4; i++) acc[mf][nf][i] = 0.0f;

    load_stage(0, 0);

    for (int s = 0; s < NSTAGE; s++) {
        if (s + 1 < NSTAGE) { load_stage(s + 1, (s + 1) & 1); cp_wait<1>(); }
        else                { cp_wait<0>(); }
        __syncthreads();

        const int buf = s & 1;
        const float* As = (const float*)(dsm + buf * STAGE_B);
        const uint32_t* Bh = (const uint32_t*)(dsm + buf * STAGE_B + A_BYTES);
        const uint32_t* Bl = (const uint32_t*)(dsm + buf * STAGE_B + A_BYTES + BP_BYTES);

#pragma unroll
        for (int ks = 0; ks < 4; ks++) {
            const int kq = ks * 8;
            uint32_t ah[2][4], al[2][4], bh[4][2], bl[4][2];
#pragma unroll
            for (int mf = 0; mf < 2; mf++) {
                int r0 = wm + mf * 16 + g;
                split_bits(As[r0 * ASTR + kq + t],           ah[mf][0], al[mf][0]);
                split_bits(As[(r0 + 8) * ASTR + kq + t],     ah[mf][1], al[mf][1]);
                split_bits(As[r0 * ASTR + kq + t + 4],       ah[mf][2], al[mf][2]);
                split_bits(As[(r0 + 8) * ASTR + kq + t + 4], ah[mf][3], al[mf][3]);
            }
#pragma unroll
            for (int nf = 0; nf < 4; nf++) {
                int n = wn + nf * 8 + g;
                bh[nf][0] = Bh[n * ASTR + kq + t];
                bh[nf][1] = Bh[n * ASTR + kq + t + 4];
                bl[nf][0] = Bl[n * ASTR + kq + t];
                bl[nf][1] = Bl[n * ASTR + kq + t + 4];
            }
#pragma unroll
            for (int mf = 0; mf < 2; mf++)
#pragma unroll
                for (int nf = 0; nf < 4; nf++) {
                    mma8(acc[mf][nf], ah[mf], bh[nf]);
                    mma8(acc[mf][nf], ah[mf], bl[nf]);
                    mma8(acc[mf][nf], al[mf], bh[nf]);
                }
        }
        __syncthreads();
    }

#pragma unroll
    for (int mf = 0; mf < 2; mf++) {
        int row0 = m0 + wm + mf * 16 + g;
#pragma unroll
        for (int nf = 0; nf < 4; nf++) {
            int col = n0 + wn + nf * 8 + 2 * t;
            float2 bv = *(const float2*)&bias[col];
            float2 o0, o1;
            o0.x = (acc[mf][nf][0] + bv.x) * scale;
            o0.y = (acc[mf][nf][1] + bv.y) * scale;
            o1.x = (acc[mf][nf][2] + bv.x) * scale;
            o1.y = (acc[mf][nf][3] + bv.y) * scale;
            *(float2*)&C[(size_t)row0 * Dm + col]       = o0;
            *(float2*)&C[(size_t)(row0 + 8) * Dm + col] = o1;
        }
    }
}

// ---------------------------------------------------------------------------
// Fused attention with tensor-core score GEMMs.
// Block = (bh, 16 q-rows), 256 threads.
// Producer: 8 warps, each m16 x n64 score tile via mma.sync tf32 (3x split).
// Modes 0/1: no max-subtraction (scores bounded; masked -> exp underflow 0,
// diagonal always present). Mode 2: max-subtraction REQUIRED (padded rows
// are uniformly ~-2e9*smk; reference softmax of them is non-degenerate).
// ---------------------------------------------------------------------------
__global__ __launch_bounds__(256) void attn_fused(
    const float* __restrict__ mask,
    const float* __restrict__ span, float* __restrict__ out)
{
    extern __shared__ float smf[];
    float* sQ  = smf + OFF_SQ;    // [16][68]
    float* sKB = smf + OFF_SKB;   // [512][20]
    float* sS  = smf + OFF_SS;    // [16][520]
    float* sRed= smf + OFF_RED;   // [16][2]
    float* sW  = smf + OFF_W;     // [8]

    int tid  = threadIdx.x;
    int lane = tid & 31;
    int warp = tid >> 5;        // 0..7
    int g    = lane >> 2, t = lane & 3;
    int wn   = warp * 64;       // producer col base
    int half = (tid >> 5) & 1;  // consumer: which 256-col half
    int qg   = tid >> 6;        // consumer: 0..3 -> q-group (4 rows each)
    int kg   = tid & 63;        // consumer: 0..63 -> 8 consecutive cols each
    int bh = blockIdx.y;
    int b = bh / Hh, h = bh % Hh;
    int q0 = blockIdx.x * 16;

    const int qmin = q0 + qg * 4, qmax = qmin + 3;
    const int c_lo = half * 256, c_hi = c_lo + 255;

    float smk[4][8];     // running soft mask (cumsum products), per consumer thread

    float rmk[8], rmq[4];
#pragma unroll
    for (int c = 0; c < 8; c++) {
        float mv = mask[b * Sq + kg * 8 + c];
        rmk[c] = (mv == -10000.0f) ? 1.0e9f : mv;
    }
#pragma unroll
    for (int r = 0; r < 4; r++) {
        float mv = mask[b * Sq + qmin + r];
        rmq[r] = (mv == -10000.0f) ? 1.0e9f : mv;
    }

    for (int mode = 0; mode < 3; mode++) {
        const float* Ap = g_proj + (size_t)(mode * 2)     * Mrows * Dm;
        const float* Bp = g_proj + (size_t)(mode * 2 + 1) * Mrows * Dm;

        const bool skipp = (mode == 0 && wn > q0 + 15) ||
                           (mode == 1 && wn + 63 < q0);
        const bool skipc = (mode == 0 && c_lo > qmax) ||
                           (mode == 1 && c_hi < qmin);

        __syncthreads();
        {   // stage Q tile 16x64
            int row = tid >> 4;
            int d4  = (tid & 15) * 4;
            *(float4*)&sQ[row * SQ_STR + d4] =
                *(const float4*)&Ap[((size_t)(b * Sq + q0 + row)) * Dm + h * Dk + d4];
        }

        float accp[8][4];
#pragma unroll
        for (int nf = 0; nf < 8; nf++)
#pragma unroll
            for (int i = 0; i < 4; i++) accp[nf][i] = 0.0f;

        const uint32_t skb_base = smem_u32(sKB);
        for (int dc = 0; dc < 4; dc++) {
            __syncthreads();
            // stage K chunk via cp.async: [512 tokens][16 d] at stride 20
#pragma unroll
            for (int i = 0; i < 8; i++) {
                int lin = i * 256 + tid;
                int tok = lin >> 2;
                int f4  = (lin & 3) * 4;
                cp16(skb_base + (uint32_t)(tok * SKB_STR + f4) * 4,
                     &Bp[((size_t)(b * Sq + tok)) * Dm + h * Dk + dc * 16 + f4]);
            }
            cp_commit();
            cp_wait<0>();
            __syncthreads();
            if (skipp) continue;
#pragma unroll
            for (int ks = 0; ks < 2; ks++) {
                const int kqg = dc * 16 + ks * 8;   // global d for Q
                const int kc  = ks * 8;             // within-chunk d for K
                uint32_t ah[4], al[4];
                split_bits(sQ[g * SQ_STR + kqg + t],           ah[0], al[0]);
                split_bits(sQ[(g + 8) * SQ_STR + kqg + t],     ah[1], al[1]);
                split_bits(sQ[g * SQ_STR + kqg + t + 4],       ah[2], al[2]);
                split_bits(sQ[(g + 8) * SQ_STR + kqg + t + 4], ah[3], al[3]);
#pragma unroll
                for (int nf = 0; nf < 8; nf++) {
                    int n = wn + nf * 8 + g;
                    uint32_t bhv[2], blv[2];
                    split_bits(sKB[n * SKB_STR + kc + t],     bhv[0], blv[0]);
                    split_bits(sKB[n * SKB_STR + kc + t + 4], bhv[1], blv[1]);
                    mma8(accp[nf], ah, bhv);
                    mma8(accp[nf], ah, blv);
                    mma8(accp[nf], al, bhv);
                }
            }
        }
        // store scores (skipped warps store zeros)
#pragma unroll
        for (int nf = 0; nf < 8; nf++) {
            int col = wn + nf * 8 + 2 * t;
            *(float2*)&sS[g * SS_STR + col]       = make_float2(accp[nf][0], accp[nf][1]);
            *(float2*)&sS[(g + 8) * SS_STR + col] = make_float2(accp[nf][2], accp[nf][3]);
        }
        __syncthreads();

        // ---------------- consumer phase ----------------
        float acc[4][8];
        if (!skipc) {
#pragma unroll
            for (int r = 0; r < 4; r++) {
                const float* srow = &sS[(qg * 4 + r) * SS_STR + kg * 8];
                float4 s0 = *(const float4*)&srow[0];
                float4 s1 = *(const float4*)&srow[4];
                acc[r][0] = s0.x; acc[r][1] = s0.y; acc[r][2] = s0.z; acc[r][3] = s0.w;
                acc[r][4] = s1.x; acc[r][5] = s1.y; acc[r][6] = s1.z; acc[r][7] = s1.w;
                int q = qmin + r;
                if (mode == 0) {
#pragma unroll
                    for (int c = 0; c < 8; c++)
                        if (kg * 8 + c > q) acc[r][c] -= 1.0e9f;
                } else if (mode == 1) {
#pragma unroll
                    for (int c = 0; c < 8; c++)
                        if (kg * 8 + c < q) acc[r][c] -= 1.0e9f;
                } else {
#pragma unroll
                    for (int c = 0; c < 8; c++)
                        acc[r][c] = (acc[r][c] - rmq[r] - rmk[c]) * smk[r][c];
                }
            }
        }

        if (mode < 2) {
            // no max-subtraction needed: unmasked scores bounded ~|2|,
            // masked entries underflow to exact 0, diagonal always unmasked.
            float tval[4];
#pragma unroll
            for (int r = 0; r < 4; r++) {
                if (skipc) {
#pragma unroll
                    for (int c = 0; c < 8; c++) acc[r][c] = 0.0f;
                    tval[r] = 0.0f;
                    if (lane == 31) sRed[(qg * 4 + r) * 2 + half] = 0.0f;
                } else {
                    float run = 0.0f;
#pragma unroll
                    for (int c = 0; c < 8; c++) {
                        run += __expf(acc[r][c]);
                        acc[r][c] = run;                 // local inclusive cumsum
                    }
                    float tv = run;
#pragma unroll
                    for (int off = 1; off < 32; off <<= 1) {
                        float u = __shfl_up_sync(0xffffffffu, tv, off);
                        if (lane >= off) tv += u;
                    }
                    tval[r] = tv;
                    if (lane == 31) sRed[(qg * 4 + r) * 2 + half] = tv;
                }
            }
            __syncthreads();
#pragma unroll
            for (int r = 0; r < 4; r++) {
                float w0 = sRed[(qg * 4 + r) * 2 + 0], w1 = sRed[(qg * 4 + r) * 2 + 1];
                float sumrow = w0 + w1;
                float tot = acc[r][7];
                float excl = (half ? w0 : 0.0f) + (tval[r] - tot);
                float inv = 1.0f / sumrow;
                if (mode == 0) {
#pragma unroll
                    for (int c = 0; c < 8; c++)
                        smk[r][c] = (excl + acc[r][c]) * inv;
                } else {
                    float base = sumrow - excl;
                    smk[r][0] *= base * inv;
#pragma unroll
                    for (int c = 1; c < 8; c++)
                        smk[r][c] *= (base - acc[r][c - 1]) * inv;
                }
            }
            __syncthreads();
        } else {
            // mode 2: max-subtraction REQUIRED (padded rows)
            float mrow[4];
#pragma unroll
            for (int r = 0; r < 4; r++) {
                float m = acc[r][0];
#pragma unroll
                for (int c = 1; c < 8; c++) m = fmaxf(m, acc[r][c]);
#pragma unroll
                for (int off = 16; off >= 1; off >>= 1)
                    m = fmaxf(m, __shfl_xor_sync(0xffffffffu, m, off));
                if (lane == 0) sRed[(qg * 4 + r) * 2 + half] = m;
            }
            __syncthreads();
#pragma unroll
            for (int r = 0; r < 4; r++)
                mrow[r] = fmaxf(sRed[(qg * 4 + r) * 2 + 0], sRed[(qg * 4 + r) * 2 + 1]);
            __syncthreads();

            float lsum = 0.0f;
#pragma unroll
            for (int r = 0; r < 4; r++) {
                float s = 0.0f;
#pragma unroll
                for (int c = 0; c < 8; c++) {
                    acc[r][c] = __expf(acc[r][c] - mrow[r]);
                    s += acc[r][c];
                }
#pragma unroll
                for (int off = 16; off >= 1; off >>= 1)
                    s += __shfl_xor_sync(0xffffffffu, s, off);
                if (lane == 0) sRed[(qg * 4 + r) * 2 + half] = s;
            }
            __syncthreads();
#pragma unroll
            for (int r = 0; r < 4; r++) {
                int q = qmin + r;
                float inv = 1.0f / (sRed[(qg * 4 + r) * 2 + 0] + sRed[(qg * 4 + r) * 2 + 1]);
                size_t oidx = ((size_t)bh * Sq + q) * Sq + kg * 8;
                size_t sidx = ((size_t)((h * Bq + b) * Sq + q)) * Sq + kg * 8;
                float4 sp0 = *(const float4*)&span[sidx];
                float4 sp1 = *(const float4*)&span[sidx + 4];
                float sp[8] = {sp0.x, sp0.y, sp0.z, sp0.w, sp1.x, sp1.y, sp1.z, sp1.w};
                float p[8];
#pragma unroll
                for (int c = 0; c < 8; c++) p[c] = acc[r][c] * inv;
                float4 o0 = {p[0], p[1], p[2], p[3]};
                float4 o1 = {p[4], p[5], p[6], p[7]};
                *(float4*)&out[oidx]     = o0;
                *(float4*)&out[oidx + 4] = o1;
#pragma unroll
                for (int c = 0; c < 8; c++)
                    lsum += softplus_neg01(p[c]) + p[c] * (1.0f - sp[c]);
            }
#pragma unroll
            for (int off = 16; off >= 1; off >>= 1)
                lsum += __shfl_xor_sync(0xffffffffu, lsum, off);
            __syncthreads();
            if (lane == 0) sW[warp] = lsum;
            __syncthreads();
            if (tid == 0) {
                float tot = 0.0f;
#pragma unroll
                for (int ww = 0; ww < 8; ww++) tot += sW[ww];
                atomicAdd(&g_loss, (double)tot);
            }
        }
    }
}

__global__ void zero_loss_kernel() { g_loss = 0.0; }

__global__ void finalize_kernel(float* out, int out_size) {
    if (out_size > NATT)
        out[NATT] = (float)(g_loss / (double)NATT);
}

// ---------------------------------------------------------------------------
extern "C" void kernel_launch(void* const* d_in, const int* in_sizes, int n_in,
                              void* d_out, int out_size)
{
    (void)in_sizes; (void)n_in;
    const float* query = (const float*)d_in[0];
    const float* key   = (const float*)d_in[1];
    const float* mask  = (const float*)d_in[2];
    const float* span  = (const float*)d_in[3];
    float* out = (float*)d_out;

    Ptr6 ws, bs;
    for (int w = 0; w < 6; w++) {
        ws.p[w] = (const float*)d_in[4 + 2 * w];
        bs.p[w] = (const float*)d_in[5 + 2 * w];
    }

    cudaFuncSetAttribute(gemm_mma, cudaFuncAttributeMaxDynamicSharedMemorySize, DYN_SMEM);
    cudaFuncSetAttribute(attn_fused, cudaFuncAttributeMaxDynamicSharedMemorySize, ATTN_SMEM_BYTES);

    transpose6<<<dim3(Dm / 32, Dm / 32, 6), dim3(32, 8)>>>(ws);
    gemm_mma<<<dim3(Mrows / BM, Dm / BN, 6), 256, DYN_SMEM>>>(query, key, bs);
    zero_loss_kernel<<<1, 1>>>();
    attn_fused<<<dim3(Sq / 16, BHn), 256, ATTN_SMEM_BYTES>>>(mask, span, out);
    finalize_kernel<<<1, 1>>>(out, out_size);
}

// round 10
// speedup vs baseline: 1.7050x; 1.1425x over previous
#include <cuda_runtime.h>
#include <cstdint>
#include <math.h>

#define Bq    8
#define Sq    512
#define Dm    768
#define Hh    12
#define Dk    64
#define BHn   (Bq*Hh)            // 96
#define Mrows (Bq*Sq)            // 4096
#define NATT  (25165824)         // B*H*S*S
#define SCALE 0.036084391824351615f   // 1/sqrt(768)
#define PW    384                // packed words per row (Dm/2)

// ---- projection GEMM tiling (bf16 m16n8k16, 3x split) ----
#define BM 128
#define BN 64
#define APL 2560                 // A plane words per stage: 128*20
#define BPL 1280                 // B plane words per stage: 64*20
#define STAGE_W (2*APL + 2*BPL)  // 7680 words
#define DYN_SMEM (2*STAGE_W*4)   // 61440 bytes
#define NSTAGE (Dm/32)           // 24

// ---- attn smem layout (4B words) ----
#define SQ_STR   36
#define SKB_STR  12
#define SS_STR   520
#define OFF_SQ   0
#define OFF_SKB  (2*16*SQ_STR)                 // 1152
#define OFF_SS   (OFF_SKB + 2*512*SKB_STR)     // 13440
#define OFF_RED  (OFF_SS + 16*SS_STR)          // 21760
#define OFF_W    (OFF_RED + 32)                // 21792
#define ATTN_SMEM_BYTES  ((OFF_W + 8)*4)       // 87200

// Scratch (device globals: allocation-free, graph-capturable)
__device__ uint32_t g_qkP[(size_t)2 * 2 * Mrows * PW];   // [mat][plane] query,key packed
__device__ uint32_t g_wP[(size_t)6 * 2 * Dm * PW];       // [w][plane] W^T packed
__device__ uint32_t g_projP[(size_t)6 * 2 * Mrows * PW]; // [w][plane] projections packed
__device__ double g_loss;

struct Ptr6 { const float* p[6]; };

// ---------------------------------------------------------------------------
// helpers
// ---------------------------------------------------------------------------
__device__ __forceinline__ uint32_t smem_u32(const void* p) {
    uint32_t a;
    asm("{ .reg .u64 t; cvta.to.shared.u64 t, %1; cvt.u32.u64 %0, t; }"
        : "=r"(a) : "l"(p));
    return a;
}
__device__ __forceinline__ void cp16(uint32_t s, const void* g) {
    asm volatile("cp.async.ca.shared.global [%0], [%1], 16;"
                 :: "r"(s), "l"(g) : "memory");
}
__device__ __forceinline__ void cp_commit() {
    asm volatile("cp.async.commit_group;" ::: "memory");
}
template <int N>
__device__ __forceinline__ void cp_wait() {
    asm volatile("cp.async.wait_group %0;" :: "n"(N) : "memory");
}
// bf16 hi/lo split (bit ops only). hi = top16 (truncate, same sign, |hi|<=|a|,
// Sterbenz => a-hi exact). lo = top16 of the residual.
__device__ __forceinline__ void splitb(float a, uint32_t& hb, uint32_t& lb) {
    uint32_t u = __float_as_uint(a);
    hb = u & 0xFFFF0000u;
    float l = a - __uint_as_float(hb);
    lb = __float_as_uint(l) & 0xFFFF0000u;
}
// pack two high-aligned bf16 bit patterns (k even in low half, k odd in high)
__device__ __forceinline__ uint32_t packw(uint32_t b0, uint32_t b1) {
    return b1 | (b0 >> 16);
}
__device__ __forceinline__ void mma16(float* c, const uint32_t* a, const uint32_t* b) {
    asm volatile(
        "mma.sync.aligned.m16n8k16.row.col.f32.bf16.bf16.f32 "
        "{%0,%1,%2,%3}, {%4,%5,%6,%7}, {%8,%9}, {%0,%1,%2,%3};"
        : "+f"(c[0]), "+f"(c[1]), "+f"(c[2]), "+f"(c[3])
        : "r"(a[0]), "r"(a[1]), "r"(a[2]), "r"(a[3]), "r"(b[0]), "r"(b[1]));
}
// ln(1+e^-p) for p in [0,1], no MUFU (Taylor, err ~1.5e-8)
__device__ __forceinline__ float softplus_neg01(float p) {
    float x = 0.5f * p;
    float y = x * x;
    float lc = y * (0.5f + y * (-8.3333333333e-2f + y * (2.2222222222e-2f +
               y * (-6.7460317460e-3f + y * (2.1869488536e-3f +
               y * (-7.3860295563e-4f))))));
    return 0.69314718056f - x + lc;
}

// ---------------------------------------------------------------------------
// Pack query/key into bf16 hi/lo planes. blockIdx.y = matrix (0 query, 1 key).
// ---------------------------------------------------------------------------
__global__ void pack_qk(const float* __restrict__ query, const float* __restrict__ key) {
    int mat = blockIdx.y;
    const float* src = mat ? key : query;
    uint32_t* hi = g_qkP + (size_t)(mat * 2 + 0) * Mrows * PW;
    uint32_t* lo = g_qkP + (size_t)(mat * 2 + 1) * Mrows * PW;
    int idx = blockIdx.x * 256 + threadIdx.x;      // word index, 0..Mrows*PW-1
    float2 v = *(const float2*)&src[(size_t)idx * 2];
    uint32_t h0, l0, h1, l1;
    splitb(v.x, h0, l0);
    splitb(v.y, h1, l1);
    hi[idx] = packw(h0, h1);
    lo[idx] = packw(l0, l1);
}

// ---------------------------------------------------------------------------
// Transpose + pack all 6 weight matrices: word j of row n packs
// W[2j][n], W[2j+1][n] (k-pair) as bf16 hi/lo planes.
// grid (Dm/32 n-tiles, Dm/32 k-tiles, 6), block (32,8)
// ---------------------------------------------------------------------------
__global__ void transpose_pack6(Ptr6 ws) {
    __shared__ float t[32][33];      // [k][n]
    int w = blockIdx.z;
    const float* W = ws.p[w];
    uint32_t* Thi = g_wP + (size_t)(w * 2 + 0) * Dm * PW;
    uint32_t* Tlo = g_wP + (size_t)(w * 2 + 1) * Dm * PW;
    int n0 = blockIdx.x * 32, k0 = blockIdx.y * 32;
    int tid = threadIdx.y * 32 + threadIdx.x;
#pragma unroll
    for (int i = 0; i < 4; i++)
        t[threadIdx.y + i * 8][threadIdx.x] =
            W[(size_t)(k0 + threadIdx.y + i * 8) * Dm + n0 + threadIdx.x];
    __syncthreads();
#pragma unroll
    for (int i = 0; i < 2; i++) {
        int lin = i * 256 + tid;     // 0..511
        int n = lin >> 4, j = lin & 15;
        uint32_t h0, l0, h1, l1;
        splitb(t[2 * j][n],     h0, l0);
        splitb(t[2 * j + 1][n], h1, l1);
        size_t idx = (size_t)(n0 + n) * PW + k0 / 2 + j;
        Thi[idx] = packw(h0, h1);
        Tlo[idx] = packw(l0, l1);
    }
}

// ---------------------------------------------------------------------------
// bf16 m16n8k16 GEMM (3x split): proj = (A @ W + bias) * scale, output packed.
// grid (32 m, 12 n, 6 gemms), 256 threads, cp.async double-buffered.
// All operands pre-packed; inner loop is LDS + MMA only.
// ---------------------------------------------------------------------------
__global__ __launch_bounds__(256, 2) void gemm_mma(Ptr6 biases)
{
    extern __shared__ uint32_t dsw[];
    const int tid = threadIdx.x, warp = tid >> 5, lane = tid & 31;
    const int g = lane >> 2, t = lane & 3;
    const int wm = (warp >> 1) * 32, wn = (warp & 1) * 32;

    const int w = blockIdx.z;
    const int mat = w & 1;                 // 0 query, 1 key
    const uint32_t* Asrc = g_qkP + (size_t)(mat * 2) * Mrows * PW;   // hi, then lo plane
    const uint32_t* Bsrc = g_wP + (size_t)(w * 2) * Dm * PW;
    uint32_t* Phi = g_projP + (size_t)(w * 2 + 0) * Mrows * PW;
    uint32_t* Plo = g_projP + (size_t)(w * 2 + 1) * Mrows * PW;
    const float* bias = biases.p[w];
    const float scale = mat ? 1.0f : SCALE;
    const int m0 = blockIdx.x * BM, n0 = blockIdx.y * BN;

    const uint32_t sb = smem_u32(dsw);

    auto load_stage = [&](int s, int buf) {
        const int kw = s * 16;             // word offset in source rows
        const uint32_t base = sb + (uint32_t)buf * STAGE_W * 4;
#pragma unroll
        for (int i = 0; i < 4; i++) {      // A: 2 planes x 128 rows x 16 words
            int id = i * 256 + tid;
            int plane = id >> 9, rem = id & 511;
            int row = rem >> 2, q = rem & 3;
            cp16(base + (uint32_t)(plane * APL + row * 20 + q * 4) * 4,
                 &Asrc[(size_t)plane * Mrows * PW + (size_t)(m0 + row) * PW + kw + q * 4]);
        }
#pragma unroll
        for (int i = 0; i < 2; i++) {      // B: 2 planes x 64 rows x 16 words
            int id = i * 256 + tid;
            int plane = id >> 8, rem = id & 255;
            int row = rem >> 2, q = rem & 3;
            cp16(base + (uint32_t)(2 * APL + plane * BPL + row * 20 + q * 4) * 4,
                 &Bsrc[(size_t)plane * Dm * PW + (size_t)(n0 + row) * PW + kw + q * 4]);
        }
        cp_commit();
    };

    float acc[2][4][4];
#pragma unroll
    for (int mf = 0; mf < 2; mf++)
#pragma unroll
        for (int nf = 0; nf < 4; nf++)
#pragma unroll
            for (int i = 0; i < 4; i++) acc[mf][nf][i] = 0.0f;

    load_stage(0, 0);

    for (int s = 0; s < NSTAGE; s++) {
        if (s + 1 < NSTAGE) { load_stage(s + 1, (s + 1) & 1); cp_wait<1>(); }
        else                { cp_wait<0>(); }
        __syncthreads();

        const uint32_t* st = dsw + (s & 1) * STAGE_W;
        const uint32_t* Ah = st;
        const uint32_t* Al = st + APL;
        const uint32_t* Bh = st + 2 * APL;
        const uint32_t* Bl = st + 2 * APL + BPL;

#pragma unroll
        for (int ks = 0; ks < 2; ks++) {
            const int kw = ks * 8;
            uint32_t ah[2][4], al[2][4], bh[4][2], bl[4][2];
#pragma unroll
            for (int mf = 0; mf < 2; mf++) {
                int r0 = wm + mf * 16 + g;
                ah[mf][0] = Ah[r0 * 20 + kw + t];
                ah[mf][1] = Ah[(r0 + 8) * 20 + kw + t];
                ah[mf][2] = Ah[r0 * 20 + kw + t + 4];
                ah[mf][3] = Ah[(r0 + 8) * 20 + kw + t + 4];
                al[mf][0] = Al[r0 * 20 + kw + t];
                al[mf][1] = Al[(r0 + 8) * 20 + kw + t];
                al[mf][2] = Al[r0 * 20 + kw + t + 4];
                al[mf][3] = Al[(r0 + 8) * 20 + kw + t + 4];
            }
#pragma unroll
            for (int nf = 0; nf < 4; nf++) {
                int n = wn + nf * 8 + g;
                bh[nf][0] = Bh[n * 20 + kw + t];
                bh[nf][1] = Bh[n * 20 + kw + t + 4];
                bl[nf][0] = Bl[n * 20 + kw + t];
                bl[nf][1] = Bl[n * 20 + kw + t + 4];
            }
#pragma unroll
            for (int mf = 0; mf < 2; mf++)
#pragma unroll
                for (int nf = 0; nf < 4; nf++) {
                    mma16(acc[mf][nf], ah[mf], bh[nf]);
                    mma16(acc[mf][nf], ah[mf], bl[nf]);
                    mma16(acc[mf][nf], al[mf], bh[nf]);
                }
        }
        __syncthreads();
    }

    // Epilogue: cols 2t,2t+1 form a k-pair -> pack directly to bf16 planes
#pragma unroll
    for (int mf = 0; mf < 2; mf++) {
        int row0 = m0 + wm + mf * 16 + g;
#pragma unroll
        for (int nf = 0; nf < 4; nf++) {
            int col = n0 + wn + nf * 8 + 2 * t;
            int wcol = (n0 + wn + nf * 8) / 2 + t;
            float2 bv = *(const float2*)&bias[col];
            float v00 = (acc[mf][nf][0] + bv.x) * scale;
            float v01 = (acc[mf][nf][1] + bv.y) * scale;
            float v10 = (acc[mf][nf][2] + bv.x) * scale;
            float v11 = (acc[mf][nf][3] + bv.y) * scale;
            uint32_t h0, l0, h1, l1;
            splitb(v00, h0, l0); splitb(v01, h1, l1);
            Phi[(size_t)row0 * PW + wcol] = packw(h0, h1);
            Plo[(size_t)row0 * PW + wcol] = packw(l0, l1);
            splitb(v10, h0, l0); splitb(v11, h1, l1);
            Phi[(size_t)(row0 + 8) * PW + wcol] = packw(h0, h1);
            Plo[(size_t)(row0 + 8) * PW + wcol] = packw(l0, l1);
        }
    }
}

// ---------------------------------------------------------------------------
// Fused attention, bf16 m16n8k16 score GEMMs on pre-packed projections.
// Block = (bh, 16 q-rows), 256 threads. Producer inner loop: LDS + MMA only.
// Modes 0/1: no max-subtraction. Mode 2: max-subtraction (padded rows).
// ---------------------------------------------------------------------------
__global__ __launch_bounds__(256) void attn_fused(
    const float* __restrict__ mask,
    const float* __restrict__ span, float* __restrict__ out)
{
    extern __shared__ uint32_t smw[];
    uint32_t* sQ  = smw + OFF_SQ;                // 2 planes x 16 x 36 words
    uint32_t* sKB = smw + OFF_SKB;               // 2 planes x 512 x 12 words
    float* sS  = (float*)(smw + OFF_SS);         // [16][520]
    float* sRed= (float*)(smw + OFF_RED);        // [16][2]
    float* sW  = (float*)(smw + OFF_W);          // [8]

    int tid  = threadIdx.x;
    int lane = tid & 31;
    int warp = tid >> 5;        // 0..7
    int g    = lane >> 2, t = lane & 3;
    int wn   = warp * 64;       // producer col base
    int half = (tid >> 5) & 1;  // consumer: which 256-col half
    int qg   = tid >> 6;        // consumer: 0..3 -> q-group (4 rows each)
    int kg   = tid & 63;        // consumer: 8 consecutive cols each
    int bh = blockIdx.y;
    int b = bh / Hh, h = bh % Hh;
    int q0 = blockIdx.x * 16;

    const int qmin = q0 + qg * 4, qmax = qmin + 3;
    const int c_lo = half * 256, c_hi = c_lo + 255;

    float smk[4][8];

    float rmk[8], rmq[4];
#pragma unroll
    for (int c = 0; c < 8; c++) {
        float mv = mask[b * Sq + kg * 8 + c];
        rmk[c] = (mv == -10000.0f) ? 1.0e9f : mv;
    }
#pragma unroll
    for (int r = 0; r < 4; r++) {
        float mv = mask[b * Sq + qmin + r];
        rmq[r] = (mv == -10000.0f) ? 1.0e9f : mv;
    }

    const uint32_t sq_b  = smem_u32(sQ);
    const uint32_t skb_b = smem_u32(sKB);

    for (int mode = 0; mode < 3; mode++) {
        const uint32_t* Qp = g_projP + (size_t)((mode * 2) * 2)     * Mrows * PW;
        const uint32_t* Kp = g_projP + (size_t)((mode * 2 + 1) * 2) * Mrows * PW;

        const bool skipp = (mode == 0 && wn > q0 + 15) ||
                           (mode == 1 && wn + 63 < q0);
        const bool skipc = (mode == 0 && c_lo > qmax) ||
                           (mode == 1 && c_hi < qmin);

        __syncthreads();
        {   // stage Q tile: 2 planes x 16 rows x 8 cp16 (32 words/row)
            int plane = tid >> 7, rem = tid & 127;
            int row = rem >> 3, q = rem & 7;
            cp16(sq_b + (uint32_t)(plane * 16 * SQ_STR + row * SQ_STR + q * 4) * 4,
                 &Qp[(size_t)plane * Mrows * PW +
                     (size_t)(b * Sq + q0 + row) * PW + h * 32 + q * 4]);
        }

        float accp[8][4];
#pragma unroll
        for (int nf = 0; nf < 8; nf++)
#pragma unroll
            for (int i = 0; i < 4; i++) accp[nf][i] = 0.0f;

        for (int dc = 0; dc < 4; dc++) {
            __syncthreads();
            // stage K chunk: 2 planes x 512 rows x 8 words (2 cp16 each)
#pragma unroll
            for (int i = 0; i < 8; i++) {
                int id = i * 256 + tid;           // 0..2047
                int plane = id >> 10, rem = id & 1023;
                int tok = rem >> 1, q = rem & 1;
                cp16(skb_b + (uint32_t)(plane * 512 * SKB_STR + tok * SKB_STR + q * 4) * 4,
                     &Kp[(size_t)plane * Mrows * PW +
                         (size_t)(b * Sq + tok) * PW + h * 32 + dc * 8 + q * 4]);
            }
            cp_commit();
            cp_wait<0>();
            __syncthreads();
            if (skipp) continue;

            const int qw = dc * 8;
            uint32_t ah[4], al[4];
            ah[0] = sQ[g * SQ_STR + qw + t];
            ah[1] = sQ[(g + 8) * SQ_STR + qw + t];
            ah[2] = sQ[g * SQ_STR + qw + t + 4];
            ah[3] = sQ[(g + 8) * SQ_STR + qw + t + 4];
            al[0] = sQ[16 * SQ_STR + g * SQ_STR + qw + t];
            al[1] = sQ[16 * SQ_STR + (g + 8) * SQ_STR + qw + t];
            al[2] = sQ[16 * SQ_STR + g * SQ_STR + qw + t + 4];
            al[3] = sQ[16 * SQ_STR + (g + 8) * SQ_STR + qw + t + 4];
#pragma unroll
            for (int nf = 0; nf < 8; nf++) {
                int n = wn + nf * 8 + g;
                uint32_t bhv[2], blv[2];
                bhv[0] = sKB[n * SKB_STR + t];
                bhv[1] = sKB[n * SKB_STR + t + 4];
                blv[0] = sKB[512 * SKB_STR + n * SKB_STR + t];
                blv[1] = sKB[512 * SKB_STR + n * SKB_STR + t + 4];
                mma16(accp[nf], ah, bhv);
                mma16(accp[nf], ah, blv);
                mma16(accp[nf], al, bhv);
            }
        }
        // store scores (skipped warps store zeros)
#pragma unroll
        for (int nf = 0; nf < 8; nf++) {
            int col = wn + nf * 8 + 2 * t;
            *(float2*)&sS[g * SS_STR + col]       = make_float2(accp[nf][0], accp[nf][1]);
            *(float2*)&sS[(g + 8) * SS_STR + col] = make_float2(accp[nf][2], accp[nf][3]);
        }
        __syncthreads();

        // ---------------- consumer phase ----------------
        float acc[4][8];
        if (!skipc) {
#pragma unroll
            for (int r = 0; r < 4; r++) {
                const float* srow = &sS[(qg * 4 + r) * SS_STR + kg * 8];
                float4 s0 = *(const float4*)&srow[0];
                float4 s1 = *(const float4*)&srow[4];
                acc[r][0] = s0.x; acc[r][1] = s0.y; acc[r][2] = s0.z; acc[r][3] = s0.w;
                acc[r][4] = s1.x; acc[r][5] = s1.y; acc[r][6] = s1.z; acc[r][7] = s1.w;
                int q = qmin + r;
                if (mode == 0) {
#pragma unroll
                    for (int c = 0; c < 8; c++)
                        if (kg * 8 + c > q) acc[r][c] -= 1.0e9f;
                } else if (mode == 1) {
#pragma unroll
                    for (int c = 0; c < 8; c++)
                        if (kg * 8 + c < q) acc[r][c] -= 1.0e9f;
                } else {
#pragma unroll
                    for (int c = 0; c < 8; c++)
                        acc[r][c] = (acc[r][c] - rmq[r] - rmk[c]) * smk[r][c];
                }
            }
        }

        if (mode < 2) {
            float tval[4];
#pragma unroll
            for (int r = 0; r < 4; r++) {
                if (skipc) {
#pragma unroll
                    for (int c = 0; c < 8; c++) acc[r][c] = 0.0f;
                    tval[r] = 0.0f;
                    if (lane == 31) sRed[(qg * 4 + r) * 2 + half] = 0.0f;
                } else {
                    float run = 0.0f;
#pragma unroll
                    for (int c = 0; c < 8; c++) {
                        run += __expf(acc[r][c]);
                        acc[r][c] = run;
                    }
                    float tv = run;
#pragma unroll
                    for (int off = 1; off < 32; off <<= 1) {
                        float u = __shfl_up_sync(0xffffffffu, tv, off);
                        if (lane >= off) tv += u;
                    }
                    tval[r] = tv;
                    if (lane == 31) sRed[(qg * 4 + r) * 2 + half] = tv;
                }
            }
            __syncthreads();
#pragma unroll
            for (int r = 0; r < 4; r++) {
                float w0 = sRed[(qg * 4 + r) * 2 + 0], w1 = sRed[(qg * 4 + r) * 2 + 1];
                float sumrow = w0 + w1;
                float tot = acc[r][7];
                float excl = (half ? w0 : 0.0f) + (tval[r] - tot);
                float inv = 1.0f / sumrow;
                if (mode == 0) {
#pragma unroll
                    for (int c = 0; c < 8; c++)
                        smk[r][c] = (excl + acc[r][c]) * inv;
                } else {
                    float base = sumrow - excl;
                    smk[r][0] *= base * inv;
#pragma unroll
                    for (int c = 1; c < 8; c++)
                        smk[r][c] *= (base - acc[r][c - 1]) * inv;
                }
            }
            __syncthreads();
        } else {
            float mrow[4];
#pragma unroll
            for (int r = 0; r < 4; r++) {
                float m = acc[r][0];
#pragma unroll
                for (int c = 1; c < 8; c++) m = fmaxf(m, acc[r][c]);
#pragma unroll
                for (int off = 16; off >= 1; off >>= 1)
                    m = fmaxf(m, __shfl_xor_sync(0xffffffffu, m, off));
                if (lane == 0) sRed[(qg * 4 + r) * 2 + half] = m;
            }
            __syncthreads();
#pragma unroll
            for (int r = 0; r < 4; r++)
                mrow[r] = fmaxf(sRed[(qg * 4 + r) * 2 + 0], sRed[(qg * 4 + r) * 2 + 1]);
            __syncthreads();

            float lsum = 0.0f;
#pragma unroll
            for (int r = 0; r < 4; r++) {
                float s = 0.0f;
#pragma unroll
                for (int c = 0; c < 8; c++) {
                    acc[r][c] = __expf(acc[r][c] - mrow[r]);
                    s += acc[r][c];
                }
#pragma unroll
                for (int off = 16; off >= 1; off >>= 1)
                    s += __shfl_xor_sync(0xffffffffu, s, off);
                if (lane == 0) sRed[(qg * 4 + r) * 2 + half] = s;
            }
            __syncthreads();
#pragma unroll
            for (int r = 0; r < 4; r++) {
                int q = qmin + r;
                float inv = 1.0f / (sRed[(qg * 4 + r) * 2 + 0] + sRed[(qg * 4 + r) * 2 + 1]);
                size_t oidx = ((size_t)bh * Sq + q) * Sq + kg * 8;
                size_t sidx = ((size_t)((h * Bq + b) * Sq + q)) * Sq + kg * 8;
                float4 sp0 = *(const float4*)&span[sidx];
                float4 sp1 = *(const float4*)&span[sidx + 4];
                float sp[8] = {sp0.x, sp0.y, sp0.z, sp0.w, sp1.x, sp1.y, sp1.z, sp1.w};
                float p[8];
#pragma unroll
                for (int c = 0; c < 8; c++) p[c] = acc[r][c] * inv;
                float4 o0 = {p[0], p[1], p[2], p[3]};
                float4 o1 = {p[4], p[5], p[6], p[7]};
                *(float4*)&out[oidx]     = o0;
                *(float4*)&out[oidx + 4] = o1;
#pragma unroll
                for (int c = 0; c < 8; c++)
                    lsum += softplus_neg01(p[c]) + p[c] * (1.0f - sp[c]);
            }
#pragma unroll
            for (int off = 16; off >= 1; off >>= 1)
                lsum += __shfl_xor_sync(0xffffffffu, lsum, off);
            __syncthreads();
            if (lane == 0) sW[warp] = lsum;
            __syncthreads();
            if (tid == 0) {
                float tot = 0.0f;
#pragma unroll
                for (int ww = 0; ww < 8; ww++) tot += sW[ww];
                atomicAdd(&g_loss, (double)tot);
            }
        }
    }
}

__global__ void zero_loss_kernel() { g_loss = 0.0; }

__global__ void finalize_kernel(float* out, int out_size) {
    if (out_size > NATT)
        out[NATT] = (float)(g_loss / (double)NATT);
}

// ---------------------------------------------------------------------------
extern "C" void kernel_launch(void* const* d_in, const int* in_sizes, int n_in,
                              void* d_out, int out_size)
{
    (void)in_sizes; (void)n_in;
    const float* query = (const float*)d_in[0];
    const float* key   = (const float*)d_in[1];
    const float* mask  = (const float*)d_in[2];
    const float* span  = (const float*)d_in[3];
    float* out = (float*)d_out;

    Ptr6 ws, bs;
    for (int w = 0; w < 6; w++) {
        ws.p[w] = (const float*)d_in[4 + 2 * w];
        bs.p[w] = (const float*)d_in[5 + 2 * w];
    }

    cudaFuncSetAttribute(gemm_mma, cudaFuncAttributeMaxDynamicSharedMemorySize, DYN_SMEM);
    cudaFuncSetAttribute(attn_fused, cudaFuncAttributeMaxDynamicSharedMemorySize, ATTN_SMEM_BYTES);

    pack_qk<<<dim3(Mrows * PW / 256, 2), 256>>>(query, key);
    transpose_pack6<<<dim3(Dm / 32, Dm / 32, 6), dim3(32, 8)>>>(ws);
    gemm_mma<<<dim3(Mrows / BM, Dm / BN, 6), 256, DYN_SMEM>>>(bs);
    zero_loss_kernel<<<1, 1>>>();
    attn_fused<<<dim3(Sq / 16, BHn), 256, ATTN_SMEM_BYTES>>>(mask, span, out);
    finalize_kernel<<<1, 1>>>(out, out_size);
}

// round 11
// speedup vs baseline: 1.7959x; 1.0533x over previous
#include <cuda_runtime.h>
#include <cstdint>
#include <math.h>

#define Bq    8
#define Sq    512
#define Dm    768
#define Hh    12
#define Dk    64
#define BHn   (Bq*Hh)            // 96
#define Mrows (Bq*Sq)            // 4096
#define NATT  (25165824)         // B*H*S*S
#define SCALE 0.036084391824351615f   // 1/sqrt(768)
#define PW    384                // packed words per row (Dm/2)

// ---- projection GEMM tiling (bf16 m16n8k16, 3x split) ----
#define BM 128
#define BN 64
#define APL 2560                 // A plane words per stage: 128*20
#define BPL 1280                 // B plane words per stage: 64*20
#define STAGE_W (2*APL + 2*BPL)  // 7680 words
#define DYN_SMEM (2*STAGE_W*4)   // 61440 bytes
#define NSTAGE (Dm/32)           // 24

// ---- attn smem layout (4B words) ----
#define SQ_STR   36
#define SKB_STR  12
#define SKB_BUF  (2*512*SKB_STR)               // 12288 words per K buffer
#define SS_STR   520
#define OFF_SQ   0
#define OFF_SKB  (2*16*SQ_STR)                 // 1152
#define OFF_SS   (OFF_SKB + 2*SKB_BUF)         // 25728
#define OFF_RED  (OFF_SS + 16*SS_STR)          // 34048
#define OFF_W    (OFF_RED + 32)                // 34080
#define ATTN_SMEM_BYTES  ((OFF_W + 8)*4)       // 136352

// Scratch (device globals: allocation-free, graph-capturable)
__device__ uint32_t g_qkP[(size_t)2 * 2 * Mrows * PW];   // [mat][plane] query,key packed
__device__ uint32_t g_wP[(size_t)6 * 2 * Dm * PW];       // [w][plane] W^T packed
__device__ uint32_t g_projP[(size_t)6 * 2 * Mrows * PW]; // [w][plane] projections packed
__device__ double g_loss;

struct Ptr6 { const float* p[6]; };

// ---------------------------------------------------------------------------
// helpers
// ---------------------------------------------------------------------------
__device__ __forceinline__ uint32_t smem_u32(const void* p) {
    uint32_t a;
    asm("{ .reg .u64 t; cvta.to.shared.u64 t, %1; cvt.u32.u64 %0, t; }"
        : "=r"(a) : "l"(p));
    return a;
}
__device__ __forceinline__ void cp16(uint32_t s, const void* g) {
    asm volatile("cp.async.ca.shared.global [%0], [%1], 16;"
                 :: "r"(s), "l"(g) : "memory");
}
__device__ __forceinline__ void cp_commit() {
    asm volatile("cp.async.commit_group;" ::: "memory");
}
template <int N>
__device__ __forceinline__ void cp_wait() {
    asm volatile("cp.async.wait_group %0;" :: "n"(N) : "memory");
}
// bf16 hi/lo split (bit ops only). hi = top16 (truncate, same sign, |hi|<=|a|,
// Sterbenz => a-hi exact). lo = top16 of the residual.
__device__ __forceinline__ void splitb(float a, uint32_t& hb, uint32_t& lb) {
    uint32_t u = __float_as_uint(a);
    hb = u & 0xFFFF0000u;
    float l = a - __uint_as_float(hb);
    lb = __float_as_uint(l) & 0xFFFF0000u;
}
// pack two high-aligned bf16 bit patterns (k even in low half, k odd in high)
__device__ __forceinline__ uint32_t packw(uint32_t b0, uint32_t b1) {
    return b1 | (b0 >> 16);
}
__device__ __forceinline__ void mma16(float* c, const uint32_t* a, const uint32_t* b) {
    asm volatile(
        "mma.sync.aligned.m16n8k16.row.col.f32.bf16.bf16.f32 "
        "{%0,%1,%2,%3}, {%4,%5,%6,%7}, {%8,%9}, {%0,%1,%2,%3};"
        : "+f"(c[0]), "+f"(c[1]), "+f"(c[2]), "+f"(c[3])
        : "r"(a[0]), "r"(a[1]), "r"(a[2]), "r"(a[3]), "r"(b[0]), "r"(b[1]));
}
// ln(1+e^-p) for p in [0,1], no MUFU (Taylor, err ~1.5e-8)
__device__ __forceinline__ float softplus_neg01(float p) {
    float x = 0.5f * p;
    float y = x * x;
    float lc = y * (0.5f + y * (-8.3333333333e-2f + y * (2.2222222222e-2f +
               y * (-6.7460317460e-3f + y * (2.1869488536e-3f +
               y * (-7.3860295563e-4f))))));
    return 0.69314718056f - x + lc;
}

// ---------------------------------------------------------------------------
// Pack query/key into bf16 hi/lo planes. blockIdx.y = matrix (0 query, 1 key).
// Also zeroes g_loss (folded launch).
// ---------------------------------------------------------------------------
__global__ void pack_qk(const float* __restrict__ query, const float* __restrict__ key) {
    if (blockIdx.x == 0 && blockIdx.y == 0 && threadIdx.x == 0) g_loss = 0.0;
    int mat = blockIdx.y;
    const float* src = mat ? key : query;
    uint32_t* hi = g_qkP + (size_t)(mat * 2 + 0) * Mrows * PW;
    uint32_t* lo = g_qkP + (size_t)(mat * 2 + 1) * Mrows * PW;
    int idx = blockIdx.x * 256 + threadIdx.x;      // word index, 0..Mrows*PW-1
    float2 v = *(const float2*)&src[(size_t)idx * 2];
    uint32_t h0, l0, h1, l1;
    splitb(v.x, h0, l0);
    splitb(v.y, h1, l1);
    hi[idx] = packw(h0, h1);
    lo[idx] = packw(l0, l1);
}

// ---------------------------------------------------------------------------
// Transpose + pack all 6 weight matrices: word j of row n packs
// W[2j][n], W[2j+1][n] (k-pair) as bf16 hi/lo planes.
// ---------------------------------------------------------------------------
__global__ void transpose_pack6(Ptr6 ws) {
    __shared__ float t[32][33];      // [k][n]
    int w = blockIdx.z;
    const float* W = ws.p[w];
    uint32_t* Thi = g_wP + (size_t)(w * 2 + 0) * Dm * PW;
    uint32_t* Tlo = g_wP + (size_t)(w * 2 + 1) * Dm * PW;
    int n0 = blockIdx.x * 32, k0 = blockIdx.y * 32;
    int tid = threadIdx.y * 32 + threadIdx.x;
#pragma unroll
    for (int i = 0; i < 4; i++)
        t[threadIdx.y + i * 8][threadIdx.x] =
            W[(size_t)(k0 + threadIdx.y + i * 8) * Dm + n0 + threadIdx.x];
    __syncthreads();
#pragma unroll
    for (int i = 0; i < 2; i++) {
        int lin = i * 256 + tid;     // 0..511
        int n = lin >> 4, j = lin & 15;
        uint32_t h0, l0, h1, l1;
        splitb(t[2 * j][n],     h0, l0);
        splitb(t[2 * j + 1][n], h1, l1);
        size_t idx = (size_t)(n0 + n) * PW + k0 / 2 + j;
        Thi[idx] = packw(h0, h1);
        Tlo[idx] = packw(l0, l1);
    }
}

// ---------------------------------------------------------------------------
// bf16 m16n8k16 GEMM (3x split): proj = (A @ W + bias) * scale, output packed.
// grid (32 m, 12 n, 6 gemms), 256 threads, cp.async double-buffered.
// ---------------------------------------------------------------------------
__global__ __launch_bounds__(256, 2) void gemm_mma(Ptr6 biases)
{
    extern __shared__ uint32_t dsw[];
    const int tid = threadIdx.x, warp = tid >> 5, lane = tid & 31;
    const int g = lane >> 2, t = lane & 3;
    const int wm = (warp >> 1) * 32, wn = (warp & 1) * 32;

    const int w = blockIdx.z;
    const int mat = w & 1;                 // 0 query, 1 key
    const uint32_t* Asrc = g_qkP + (size_t)(mat * 2) * Mrows * PW;   // hi, then lo plane
    const uint32_t* Bsrc = g_wP + (size_t)(w * 2) * Dm * PW;
    uint32_t* Phi = g_projP + (size_t)(w * 2 + 0) * Mrows * PW;
    uint32_t* Plo = g_projP + (size_t)(w * 2 + 1) * Mrows * PW;
    const float* bias = biases.p[w];
    const float scale = mat ? 1.0f : SCALE;
    const int m0 = blockIdx.x * BM, n0 = blockIdx.y * BN;

    const uint32_t sb = smem_u32(dsw);

    auto load_stage = [&](int s, int buf) {
        const int kw = s * 16;             // word offset in source rows
        const uint32_t base = sb + (uint32_t)buf * STAGE_W * 4;
#pragma unroll
        for (int i = 0; i < 4; i++) {      // A: 2 planes x 128 rows x 16 words
            int id = i * 256 + tid;
            int plane = id >> 9, rem = id & 511;
            int row = rem >> 2, q = rem & 3;
            cp16(base + (uint32_t)(plane * APL + row * 20 + q * 4) * 4,
                 &Asrc[(size_t)plane * Mrows * PW + (size_t)(m0 + row) * PW + kw + q * 4]);
        }
#pragma unroll
        for (int i = 0; i < 2; i++) {      // B: 2 planes x 64 rows x 16 words
            int id = i * 256 + tid;
            int plane = id >> 8, rem = id & 255;
            int row = rem >> 2, q = rem & 3;
            cp16(base + (uint32_t)(2 * APL + plane * BPL + row * 20 + q * 4) * 4,
                 &Bsrc[(size_t)plane * Dm * PW + (size_t)(n0 + row) * PW + kw + q * 4]);
        }
        cp_commit();
    };

    float acc[2][4][4];
#pragma unroll
    for (int mf = 0; mf < 2; mf++)
#pragma unroll
        for (int nf = 0; nf < 4; nf++)
#pragma unroll
            for (int i = 0; i < 4; i++) acc[mf][nf][i] = 0.0f;

    load_stage(0, 0);

    for (int s = 0; s < NSTAGE; s++) {
        if (s + 1 < NSTAGE) { load_stage(s + 1, (s + 1) & 1); cp_wait<1>(); }
        else                { cp_wait<0>(); }
        __syncthreads();

        const uint32_t* st = dsw + (s & 1) * STAGE_W;
        const uint32_t* Ah = st;
        const uint32_t* Al = st + APL;
        const uint32_t* Bh = st + 2 * APL;
        const uint32_t* Bl = st + 2 * APL + BPL;

#pragma unroll
        for (int ks = 0; ks < 2; ks++) {
            const int kw = ks * 8;
            uint32_t ah[2][4], al[2][4], bh[4][2], bl[4][2];
#pragma unroll
            for (int mf = 0; mf < 2; mf++) {
                int r0 = wm + mf * 16 + g;
                ah[mf][0] = Ah[r0 * 20 + kw + t];
                ah[mf][1] = Ah[(r0 + 8) * 20 + kw + t];
                ah[mf][2] = Ah[r0 * 20 + kw + t + 4];
                ah[mf][3] = Ah[(r0 + 8) * 20 + kw + t + 4];
                al[mf][0] = Al[r0 * 20 + kw + t];
                al[mf][1] = Al[(r0 + 8) * 20 + kw + t];
                al[mf][2] = Al[r0 * 20 + kw + t + 4];
                al[mf][3] = Al[(r0 + 8) * 20 + kw + t + 4];
            }
#pragma unroll
            for (int nf = 0; nf < 4; nf++) {
                int n = wn + nf * 8 + g;
                bh[nf][0] = Bh[n * 20 + kw + t];
                bh[nf][1] = Bh[n * 20 + kw + t + 4];
                bl[nf][0] = Bl[n * 20 + kw + t];
                bl[nf][1] = Bl[n * 20 + kw + t + 4];
            }
#pragma unroll
            for (int mf = 0; mf < 2; mf++)
#pragma unroll
                for (int nf = 0; nf < 4; nf++) {
                    mma16(acc[mf][nf], ah[mf], bh[nf]);
                    mma16(acc[mf][nf], ah[mf], bl[nf]);
                    mma16(acc[mf][nf], al[mf], bh[nf]);
                }
        }
        __syncthreads();
    }

    // Epilogue: cols 2t,2t+1 form a k-pair -> pack directly to bf16 planes
#pragma unroll
    for (int mf = 0; mf < 2; mf++) {
        int row0 = m0 + wm + mf * 16 + g;
#pragma unroll
        for (int nf = 0; nf < 4; nf++) {
            int col = n0 + wn + nf * 8 + 2 * t;
            int wcol = (n0 + wn + nf * 8) / 2 + t;
            float2 bv = *(const float2*)&bias[col];
            float v00 = (acc[mf][nf][0] + bv.x) * scale;
            float v01 = (acc[mf][nf][1] + bv.y) * scale;
            float v10 = (acc[mf][nf][2] + bv.x) * scale;
            float v11 = (acc[mf][nf][3] + bv.y) * scale;
            uint32_t h0, l0, h1, l1;
            splitb(v00, h0, l0); splitb(v01, h1, l1);
            Phi[(size_t)row0 * PW + wcol] = packw(h0, h1);
            Plo[(size_t)row0 * PW + wcol] = packw(l0, l1);
            splitb(v10, h0, l0); splitb(v11, h1, l1);
            Phi[(size_t)(row0 + 8) * PW + wcol] = packw(h0, h1);
            Plo[(size_t)(row0 + 8) * PW + wcol] = packw(l0, l1);
        }
    }
}

// ---------------------------------------------------------------------------
// Fused attention, bf16 m16n8k16 score GEMMs, double-buffered K staging.
// Block = (bh, 16 q-rows), 256 threads.
// ---------------------------------------------------------------------------
__global__ __launch_bounds__(256) void attn_fused(
    const float* __restrict__ mask,
    const float* __restrict__ span, float* __restrict__ out)
{
    extern __shared__ uint32_t smw[];
    uint32_t* sQ  = smw + OFF_SQ;                // 2 planes x 16 x 36 words
    uint32_t* sKB = smw + OFF_SKB;               // 2 bufs x (2 planes x 512 x 12)
    float* sS  = (float*)(smw + OFF_SS);         // [16][520]
    float* sRed= (float*)(smw + OFF_RED);        // [16][2]
    float* sW  = (float*)(smw + OFF_W);          // [8]

    int tid  = threadIdx.x;
    int lane = tid & 31;
    int warp = tid >> 5;        // 0..7
    int g    = lane >> 2, t = lane & 3;
    int wn   = warp * 64;       // producer col base
    int half = (tid >> 5) & 1;  // consumer: which 256-col half
    int qg   = tid >> 6;        // consumer: 0..3 -> q-group (4 rows each)
    int kg   = tid & 63;        // consumer: 8 consecutive cols each
    int bh = blockIdx.y;
    int b = bh / Hh, h = bh % Hh;
    int q0 = blockIdx.x * 16;

    const int qmin = q0 + qg * 4, qmax = qmin + 3;
    const int c_lo = half * 256, c_hi = c_lo + 255;

    float smk[4][8];

    float rmk[8], rmq[4];
#pragma unroll
    for (int c = 0; c < 8; c++) {
        float mv = mask[b * Sq + kg * 8 + c];
        rmk[c] = (mv == -10000.0f) ? 1.0e9f : mv;
    }
#pragma unroll
    for (int r = 0; r < 4; r++) {
        float mv = mask[b * Sq + qmin + r];
        rmq[r] = (mv == -10000.0f) ? 1.0e9f : mv;
    }

    const uint32_t sq_b  = smem_u32(sQ);
    const uint32_t skb_b = smem_u32(sKB);

    for (int mode = 0; mode < 3; mode++) {
        const uint32_t* Qp = g_projP + (size_t)((mode * 2) * 2)     * Mrows * PW;
        const uint32_t* Kp = g_projP + (size_t)((mode * 2 + 1) * 2) * Mrows * PW;

        const bool skipp = (mode == 0 && wn > q0 + 15) ||
                           (mode == 1 && wn + 63 < q0);
        const bool skipc = (mode == 0 && c_lo > qmax) ||
                           (mode == 1 && c_hi < qmin);

        // stage K chunk dc into buffer buf
        auto stageK = [&](int dc, int buf) {
            const uint32_t kb = skb_b + (uint32_t)buf * SKB_BUF * 4;
#pragma unroll
            for (int i = 0; i < 8; i++) {
                int id = i * 256 + tid;           // 0..2047
                int plane = id >> 10, rem = id & 1023;
                int tok = rem >> 1, q = rem & 1;
                cp16(kb + (uint32_t)(plane * 512 * SKB_STR + tok * SKB_STR + q * 4) * 4,
                     &Kp[(size_t)plane * Mrows * PW +
                         (size_t)(b * Sq + tok) * PW + h * 32 + dc * 8 + q * 4]);
            }
            cp_commit();
        };

        __syncthreads();   // protect sQ/sS reuse from previous mode
        {   // stage Q tile: 2 planes x 16 rows (32 words/row)
            int plane = tid >> 7, rem = tid & 127;
            int row = rem >> 3, q = rem & 7;
            cp16(sq_b + (uint32_t)(plane * 16 * SQ_STR + row * SQ_STR + q * 4) * 4,
                 &Qp[(size_t)plane * Mrows * PW +
                     (size_t)(b * Sq + q0 + row) * PW + h * 32 + q * 4]);
        }
        stageK(0, 0);      // commits Q + K0 as one group

        float accp[8][4];
#pragma unroll
        for (int nf = 0; nf < 8; nf++)
#pragma unroll
            for (int i = 0; i < 4; i++) accp[nf][i] = 0.0f;

        for (int dc = 0; dc < 4; dc++) {
            if (dc < 3) { stageK(dc + 1, (dc + 1) & 1); cp_wait<1>(); }
            else        { cp_wait<0>(); }
            __syncthreads();

            if (!skipp) {
                const uint32_t* kbuf = sKB + (dc & 1) * SKB_BUF;
                const int qw = dc * 8;
                uint32_t ah[4], al[4];
                ah[0] = sQ[g * SQ_STR + qw + t];
                ah[1] = sQ[(g + 8) * SQ_STR + qw + t];
                ah[2] = sQ[g * SQ_STR + qw + t + 4];
                ah[3] = sQ[(g + 8) * SQ_STR + qw + t + 4];
                al[0] = sQ[16 * SQ_STR + g * SQ_STR + qw + t];
                al[1] = sQ[16 * SQ_STR + (g + 8) * SQ_STR + qw + t];
                al[2] = sQ[16 * SQ_STR + g * SQ_STR + qw + t + 4];
                al[3] = sQ[16 * SQ_STR + (g + 8) * SQ_STR + qw + t + 4];
#pragma unroll
                for (int nf = 0; nf < 8; nf++) {
                    int n = wn + nf * 8 + g;
                    uint32_t bhv[2], blv[2];
                    bhv[0] = kbuf[n * SKB_STR + t];
                    bhv[1] = kbuf[n * SKB_STR + t + 4];
                    blv[0] = kbuf[512 * SKB_STR + n * SKB_STR + t];
                    blv[1] = kbuf[512 * SKB_STR + n * SKB_STR + t + 4];
                    mma16(accp[nf], ah, bhv);
                    mma16(accp[nf], ah, blv);
                    mma16(accp[nf], al, bhv);
                }
            }
            __syncthreads();   // all reads of buf (dc&1) done before it is re-staged
        }
        // store scores (skipped warps store zeros)
#pragma unroll
        for (int nf = 0; nf < 8; nf++) {
            int col = wn + nf * 8 + 2 * t;
            *(float2*)&sS[g * SS_STR + col]       = make_float2(accp[nf][0], accp[nf][1]);
            *(float2*)&sS[(g + 8) * SS_STR + col] = make_float2(accp[nf][2], accp[nf][3]);
        }
        __syncthreads();

        // ---------------- consumer phase ----------------
        float acc[4][8];
        if (!skipc) {
#pragma unroll
            for (int r = 0; r < 4; r++) {
                const float* srow = &sS[(qg * 4 + r) * SS_STR + kg * 8];
                float4 s0 = *(const float4*)&srow[0];
                float4 s1 = *(const float4*)&srow[4];
                acc[r][0] = s0.x; acc[r][1] = s0.y; acc[r][2] = s0.z; acc[r][3] = s0.w;
                acc[r][4] = s1.x; acc[r][5] = s1.y; acc[r][6] = s1.z; acc[r][7] = s1.w;
                int q = qmin + r;
                if (mode == 0) {
#pragma unroll
                    for (int c = 0; c < 8; c++)
                        if (kg * 8 + c > q) acc[r][c] -= 1.0e9f;
                } else if (mode == 1) {
#pragma unroll
                    for (int c = 0; c < 8; c++)
                        if (kg * 8 + c < q) acc[r][c] -= 1.0e9f;
                } else {
#pragma unroll
                    for (int c = 0; c < 8; c++)
                        acc[r][c] = (acc[r][c] - rmq[r] - rmk[c]) * smk[r][c];
                }
            }
        }

        if (mode < 2) {
            float tval[4];
#pragma unroll
            for (int r = 0; r < 4; r++) {
                if (skipc) {
#pragma unroll
                    for (int c = 0; c < 8; c++) acc[r][c] = 0.0f;
                    tval[r] = 0.0f;
                    if (lane == 31) sRed[(qg * 4 + r) * 2 + half] = 0.0f;
                } else {
                    float run = 0.0f;
#pragma unroll
                    for (int c = 0; c < 8; c++) {
                        run += __expf(acc[r][c]);
                        acc[r][c] = run;
                    }
                    float tv = run;
#pragma unroll
                    for (int off = 1; off < 32; off <<= 1) {
                        float u = __shfl_up_sync(0xffffffffu, tv, off);
                        if (lane >= off) tv += u;
                    }
                    tval[r] = tv;
                    if (lane == 31) sRed[(qg * 4 + r) * 2 + half] = tv;
                }
            }
            __syncthreads();
#pragma unroll
            for (int r = 0; r < 4; r++) {
                float w0 = sRed[(qg * 4 + r) * 2 + 0], w1 = sRed[(qg * 4 + r) * 2 + 1];
                float sumrow = w0 + w1;
                float tot = acc[r][7];
                float excl = (half ? w0 : 0.0f) + (tval[r] - tot);
                float inv = 1.0f / sumrow;
                if (mode == 0) {
#pragma unroll
                    for (int c = 0; c < 8; c++)
                        smk[r][c] = (excl + acc[r][c]) * inv;
                } else {
                    float base = sumrow - excl;
                    smk[r][0] *= base * inv;
#pragma unroll
                    for (int c = 1; c < 8; c++)
                        smk[r][c] *= (base - acc[r][c - 1]) * inv;
                }
            }
            __syncthreads();
        } else {
            float mrow[4];
#pragma unroll
            for (int r = 0; r < 4; r++) {
                float m = acc[r][0];
#pragma unroll
                for (int c = 1; c < 8; c++) m = fmaxf(m, acc[r][c]);
#pragma unroll
                for (int off = 16; off >= 1; off >>= 1)
                    m = fmaxf(m, __shfl_xor_sync(0xffffffffu, m, off));
                if (lane == 0) sRed[(qg * 4 + r) * 2 + half] = m;
            }
            __syncthreads();
#pragma unroll
            for (int r = 0; r < 4; r++)
                mrow[r] = fmaxf(sRed[(qg * 4 + r) * 2 + 0], sRed[(qg * 4 + r) * 2 + 1]);
            __syncthreads();

            float lsum = 0.0f;
#pragma unroll
            for (int r = 0; r < 4; r++) {
                float s = 0.0f;
#pragma unroll
                for (int c = 0; c < 8; c++) {
                    acc[r][c] = __expf(acc[r][c] - mrow[r]);
                    s += acc[r][c];
                }
#pragma unroll
                for (int off = 16; off >= 1; off >>= 1)
                    s += __shfl_xor_sync(0xffffffffu, s, off);
                if (lane == 0) sRed[(qg * 4 + r) * 2 + half] = s;
            }
            __syncthreads();
#pragma unroll
            for (int r = 0; r < 4; r++) {
                int q = qmin + r;
                float inv = 1.0f / (sRed[(qg * 4 + r) * 2 + 0] + sRed[(qg * 4 + r) * 2 + 1]);
                size_t oidx = ((size_t)bh * Sq + q) * Sq + kg * 8;
                size_t sidx = ((size_t)((h * Bq + b) * Sq + q)) * Sq + kg * 8;
                float4 sp0 = *(const float4*)&span[sidx];
                float4 sp1 = *(const float4*)&span[sidx + 4];
                float sp[8] = {sp0.x, sp0.y, sp0.z, sp0.w, sp1.x, sp1.y, sp1.z, sp1.w};
                float p[8];
#pragma unroll
                for (int c = 0; c < 8; c++) p[c] = acc[r][c] * inv;
                float4 o0 = {p[0], p[1], p[2], p[3]};
                float4 o1 = {p[4], p[5], p[6], p[7]};
                *(float4*)&out[oidx]     = o0;
                *(float4*)&out[oidx + 4] = o1;
#pragma unroll
                for (int c = 0; c < 8; c++)
                    lsum += softplus_neg01(p[c]) + p[c] * (1.0f - sp[c]);
            }
#pragma unroll
            for (int off = 16; off >= 1; off >>= 1)
                lsum += __shfl_xor_sync(0xffffffffu, lsum, off);
            __syncthreads();
            if (lane == 0) sW[warp] = lsum;
            __syncthreads();
            if (tid == 0) {
                float tot = 0.0f;
#pragma unroll
                for (int ww = 0; ww < 8; ww++) tot += sW[ww];
                atomicAdd(&g_loss, (double)tot);
            }
        }
    }
}

__global__ void finalize_kernel(float* out, int out_size) {
    if (out_size > NATT)
        out[NATT] = (float)(g_loss / (double)NATT);
}

// ---------------------------------------------------------------------------
extern "C" void kernel_launch(void* const* d_in, const int* in_sizes, int n_in,
                              void* d_out, int out_size)
{
    (void)in_sizes; (void)n_in;
    const float* query = (const float*)d_in[0];
    const float* key   = (const float*)d_in[1];
    const float* mask  = (const float*)d_in[2];
    const float* span  = (const float*)d_in[3];
    float* out = (float*)d_out;

    Ptr6 ws, bs;
    for (int w = 0; w < 6; w++) {
        ws.p[w] = (const float*)d_in[4 + 2 * w];
        bs.p[w] = (const float*)d_in[5 + 2 * w];
    }

    cudaFuncSetAttribute(gemm_mma, cudaFuncAttributeMaxDynamicSharedMemorySize, DYN_SMEM);
    cudaFuncSetAttribute(attn_fused, cudaFuncAttributeMaxDynamicSharedMemorySize, ATTN_SMEM_BYTES);

    pack_qk<<<dim3(Mrows * PW / 256, 2), 256>>>(query, key);
    transpose_pack6<<<dim3(Dm / 32, Dm / 32, 6), dim3(32, 8)>>>(ws);
    gemm_mma<<<dim3(Mrows / BM, Dm / BN, 6), 256, DYN_SMEM>>>(bs);
    attn_fused<<<dim3(Sq / 16, BHn), 256, ATTN_SMEM_BYTES>>>(mask, span, out);
    finalize_kernel<<<1, 1>>>(out, out_size);
}

// round 12
// speedup vs baseline: 2.2095x; 1.2303x over previous
#include <cuda_runtime.h>
#include <cstdint>
#include <math.h>

#define Bq    8
#define Sq    512
#define Dm    768
#define Hh    12
#define Dk    64
#define BHn   (Bq*Hh)            // 96
#define Mrows (Bq*Sq)            // 4096
#define NATT  (25165824)         // B*H*S*S
#define SCALE 0.036084391824351615f   // 1/sqrt(768)
#define PW    384                // packed words per row (Dm/2)

// ---- projection GEMM tiling (bf16 m16n8k16, 3x split) ----
#define BM 128
#define BN 64
#define APL 2560                 // A plane words per stage: 128*20
#define BPL 1280                 // B plane words per stage: 64*20
#define STAGE_W (2*APL + 2*BPL)  // 7680 words
#define DYN_SMEM (2*STAGE_W*4)   // 61440 bytes
#define NSTAGE (Dm/32)           // 24

// ---- attn smem layout (4B words), 32 q-rows per block ----
#define QROWS 32
#define KBUF  9216               // K chunk buffer: 2 planes x 128 tok x 36 words
#define SS_STR 520
#define OFF_SQ   0                               // 2 planes x 32 x 36 = 2304
#define OFF_SKB  2304                            // 2 bufs x 9216 = 18432
#define OFF_SS   20736                           // 32 x 520 = 16640
#define OFF_SMK  37376                           // 32 x 512 = 16384
#define OFF_RED  53760                           // 32
#define OFF_W    53792                           // 8
#define ATTN_SMEM_BYTES  ((OFF_W + 8)*4)         // 215200

// Scratch (device globals: allocation-free, graph-capturable)
__device__ uint32_t g_qkP[(size_t)2 * 2 * Mrows * PW];   // [mat][plane] query,key packed
__device__ uint32_t g_wP[(size_t)6 * 2 * Dm * PW];       // [w][plane] W^T packed
__device__ uint32_t g_projP[(size_t)6 * 2 * Mrows * PW]; // [w][plane] projections packed
__device__ double g_loss;

struct Ptr6 { const float* p[6]; };

// ---------------------------------------------------------------------------
// helpers
// ---------------------------------------------------------------------------
__device__ __forceinline__ uint32_t smem_u32(const void* p) {
    uint32_t a;
    asm("{ .reg .u64 t; cvta.to.shared.u64 t, %1; cvt.u32.u64 %0, t; }"
        : "=r"(a) : "l"(p));
    return a;
}
__device__ __forceinline__ void cp16(uint32_t s, const void* g) {
    asm volatile("cp.async.ca.shared.global [%0], [%1], 16;"
                 :: "r"(s), "l"(g) : "memory");
}
__device__ __forceinline__ void cp_commit() {
    asm volatile("cp.async.commit_group;" ::: "memory");
}
template <int N>
__device__ __forceinline__ void cp_wait() {
    asm volatile("cp.async.wait_group %0;" :: "n"(N) : "memory");
}
// bf16 hi/lo split (bit ops only; Sterbenz => a-hi exact)
__device__ __forceinline__ void splitb(float a, uint32_t& hb, uint32_t& lb) {
    uint32_t u = __float_as_uint(a);
    hb = u & 0xFFFF0000u;
    float l = a - __uint_as_float(hb);
    lb = __float_as_uint(l) & 0xFFFF0000u;
}
__device__ __forceinline__ uint32_t packw(uint32_t b0, uint32_t b1) {
    return b1 | (b0 >> 16);
}
__device__ __forceinline__ void mma16(float* c, const uint32_t* a, const uint32_t* b) {
    asm volatile(
        "mma.sync.aligned.m16n8k16.row.col.f32.bf16.bf16.f32 "
        "{%0,%1,%2,%3}, {%4,%5,%6,%7}, {%8,%9}, {%0,%1,%2,%3};"
        : "+f"(c[0]), "+f"(c[1]), "+f"(c[2]), "+f"(c[3])
        : "r"(a[0]), "r"(a[1]), "r"(a[2]), "r"(a[3]), "r"(b[0]), "r"(b[1]));
}
// ln(1+e^-p) for p in [0,1], no MUFU (Taylor, err ~1.5e-8)
__device__ __forceinline__ float softplus_neg01(float p) {
    float x = 0.5f * p;
    float y = x * x;
    float lc = y * (0.5f + y * (-8.3333333333e-2f + y * (2.2222222222e-2f +
               y * (-6.7460317460e-3f + y * (2.1869488536e-3f +
               y * (-7.3860295563e-4f))))));
    return 0.69314718056f - x + lc;
}

// ---------------------------------------------------------------------------
// Pack query/key into bf16 hi/lo planes (also zeroes g_loss).
// ---------------------------------------------------------------------------
__global__ void pack_qk(const float* __restrict__ query, const float* __restrict__ key) {
    if (blockIdx.x == 0 && blockIdx.y == 0 && threadIdx.x == 0) g_loss = 0.0;
    int mat = blockIdx.y;
    const float* src = mat ? key : query;
    uint32_t* hi = g_qkP + (size_t)(mat * 2 + 0) * Mrows * PW;
    uint32_t* lo = g_qkP + (size_t)(mat * 2 + 1) * Mrows * PW;
    int idx = blockIdx.x * 256 + threadIdx.x;
    float2 v = *(const float2*)&src[(size_t)idx * 2];
    uint32_t h0, l0, h1, l1;
    splitb(v.x, h0, l0);
    splitb(v.y, h1, l1);
    hi[idx] = packw(h0, h1);
    lo[idx] = packw(l0, l1);
}

// ---------------------------------------------------------------------------
// Transpose + pack all 6 weight matrices as bf16 hi/lo planes (n-major).
// ---------------------------------------------------------------------------
__global__ void transpose_pack6(Ptr6 ws) {
    __shared__ float t[32][33];
    int w = blockIdx.z;
    const float* W = ws.p[w];
    uint32_t* Thi = g_wP + (size_t)(w * 2 + 0) * Dm * PW;
    uint32_t* Tlo = g_wP + (size_t)(w * 2 + 1) * Dm * PW;
    int n0 = blockIdx.x * 32, k0 = blockIdx.y * 32;
    int tid = threadIdx.y * 32 + threadIdx.x;
#pragma unroll
    for (int i = 0; i < 4; i++)
        t[threadIdx.y + i * 8][threadIdx.x] =
            W[(size_t)(k0 + threadIdx.y + i * 8) * Dm + n0 + threadIdx.x];
    __syncthreads();
#pragma unroll
    for (int i = 0; i < 2; i++) {
        int lin = i * 256 + tid;
        int n = lin >> 4, j = lin & 15;
        uint32_t h0, l0, h1, l1;
        splitb(t[2 * j][n],     h0, l0);
        splitb(t[2 * j + 1][n], h1, l1);
        size_t idx = (size_t)(n0 + n) * PW + k0 / 2 + j;
        Thi[idx] = packw(h0, h1);
        Tlo[idx] = packw(l0, l1);
    }
}

// ---------------------------------------------------------------------------
// bf16 m16n8k16 GEMM (3x split): proj = (A @ W + bias) * scale, output packed.
// ---------------------------------------------------------------------------
__global__ __launch_bounds__(256, 2) void gemm_mma(Ptr6 biases)
{
    extern __shared__ uint32_t dsw[];
    const int tid = threadIdx.x, warp = tid >> 5, lane = tid & 31;
    const int g = lane >> 2, t = lane & 3;
    const int wm = (warp >> 1) * 32, wn = (warp & 1) * 32;

    const int w = blockIdx.z;
    const int mat = w & 1;
    const uint32_t* Asrc = g_qkP + (size_t)(mat * 2) * Mrows * PW;
    const uint32_t* Bsrc = g_wP + (size_t)(w * 2) * Dm * PW;
    uint32_t* Phi = g_projP + (size_t)(w * 2 + 0) * Mrows * PW;
    uint32_t* Plo = g_projP + (size_t)(w * 2 + 1) * Mrows * PW;
    const float* bias = biases.p[w];
    const float scale = mat ? 1.0f : SCALE;
    const int m0 = blockIdx.x * BM, n0 = blockIdx.y * BN;

    const uint32_t sb = smem_u32(dsw);

    auto load_stage = [&](int s, int buf) {
        const int kw = s * 16;
        const uint32_t base = sb + (uint32_t)buf * STAGE_W * 4;
#pragma unroll
        for (int i = 0; i < 4; i++) {
            int id = i * 256 + tid;
            int plane = id >> 9, rem = id & 511;
            int row = rem >> 2, q = rem & 3;
            cp16(base + (uint32_t)(plane * APL + row * 20 + q * 4) * 4,
                 &Asrc[(size_t)plane * Mrows * PW + (size_t)(m0 + row) * PW + kw + q * 4]);
        }
#pragma unroll
        for (int i = 0; i < 2; i++) {
            int id = i * 256 + tid;
            int plane = id >> 8, rem = id & 255;
            int row = rem >> 2, q = rem & 3;
            cp16(base + (uint32_t)(2 * APL + plane * BPL + row * 20 + q * 4) * 4,
                 &Bsrc[(size_t)plane * Dm * PW + (size_t)(n0 + row) * PW + kw + q * 4]);
        }
        cp_commit();
    };

    float acc[2][4][4];
#pragma unroll
    for (int mf = 0; mf < 2; mf++)
#pragma unroll
        for (int nf = 0; nf < 4; nf++)
#pragma unroll
            for (int i = 0; i < 4; i++) acc[mf][nf][i] = 0.0f;

    load_stage(0, 0);

    for (int s = 0; s < NSTAGE; s++) {
        if (s + 1 < NSTAGE) { load_stage(s + 1, (s + 1) & 1); cp_wait<1>(); }
        else                { cp_wait<0>(); }
        __syncthreads();

        const uint32_t* st = dsw + (s & 1) * STAGE_W;
        const uint32_t* Ah = st;
        const uint32_t* Al = st + APL;
        const uint32_t* Bh = st + 2 * APL;
        const uint32_t* Bl = st + 2 * APL + BPL;

#pragma unroll
        for (int ks = 0; ks < 2; ks++) {
            const int kw = ks * 8;
            uint32_t ah[2][4], al[2][4], bh[4][2], bl[4][2];
#pragma unroll
            for (int mf = 0; mf < 2; mf++) {
                int r0 = wm + mf * 16 + g;
                ah[mf][0] = Ah[r0 * 20 + kw + t];
                ah[mf][1] = Ah[(r0 + 8) * 20 + kw + t];
                ah[mf][2] = Ah[r0 * 20 + kw + t + 4];
                ah[mf][3] = Ah[(r0 + 8) * 20 + kw + t + 4];
                al[mf][0] = Al[r0 * 20 + kw + t];
                al[mf][1] = Al[(r0 + 8) * 20 + kw + t];
                al[mf][2] = Al[r0 * 20 + kw + t + 4];
                al[mf][3] = Al[(r0 + 8) * 20 + kw + t + 4];
            }
#pragma unroll
            for (int nf = 0; nf < 4; nf++) {
                int n = wn + nf * 8 + g;
                bh[nf][0] = Bh[n * 20 + kw + t];
                bh[nf][1] = Bh[n * 20 + kw + t + 4];
                bl[nf][0] = Bl[n * 20 + kw + t];
                bl[nf][1] = Bl[n * 20 + kw + t + 4];
            }
#pragma unroll
            for (int mf = 0; mf < 2; mf++)
#pragma unroll
                for (int nf = 0; nf < 4; nf++) {
                    mma16(acc[mf][nf], ah[mf], bh[nf]);
                    mma16(acc[mf][nf], ah[mf], bl[nf]);
                    mma16(acc[mf][nf], al[mf], bh[nf]);
                }
        }
        __syncthreads();
    }

#pragma unroll
    for (int mf = 0; mf < 2; mf++) {
        int row0 = m0 + wm + mf * 16 + g;
#pragma unroll
        for (int nf = 0; nf < 4; nf++) {
            int col = n0 + wn + nf * 8 + 2 * t;
            int wcol = (n0 + wn + nf * 8) / 2 + t;
            float2 bv = *(const float2*)&bias[col];
            float v00 = (acc[mf][nf][0] + bv.x) * scale;
            float v01 = (acc[mf][nf][1] + bv.y) * scale;
            float v10 = (acc[mf][nf][2] + bv.x) * scale;
            float v11 = (acc[mf][nf][3] + bv.y) * scale;
            uint32_t h0, l0, h1, l1;
            splitb(v00, h0, l0); splitb(v01, h1, l1);
            Phi[(size_t)row0 * PW + wcol] = packw(h0, h1);
            Plo[(size_t)row0 * PW + wcol] = packw(l0, l1);
            splitb(v10, h0, l0); splitb(v11, h1, l1);
            Phi[(size_t)(row0 + 8) * PW + wcol] = packw(h0, h1);
            Plo[(size_t)(row0 + 8) * PW + wcol] = packw(l0, l1);
        }
    }
}

// ---------------------------------------------------------------------------
// Fused attention: 32 q-rows per block, token-chunked (128-token) K staging,
// triangle chunk skipping, smk in smem, two-pass consumer.
// ---------------------------------------------------------------------------
__global__ __launch_bounds__(256) void attn_fused(
    const float* __restrict__ mask,
    const float* __restrict__ span, float* __restrict__ out)
{
    extern __shared__ uint32_t smw[];
    uint32_t* sQ  = smw + OFF_SQ;
    uint32_t* sKB = smw + OFF_SKB;
    float* sS  = (float*)(smw + OFF_SS);
    float* sMK = (float*)(smw + OFF_SMK);
    float* sRed= (float*)(smw + OFF_RED);
    float* sW  = (float*)(smw + OFF_W);

    int tid  = threadIdx.x;
    int lane = tid & 31;
    int warp = tid >> 5;        // 0..7
    int g    = lane >> 2, t = lane & 3;
    int rt   = warp >> 2;       // producer row tile (0/1)
    int ct   = warp & 3;        // producer 32-col tile within 128-token chunk
    int half = (tid >> 5) & 1;  // consumer: which 256-col half
    int qg   = tid >> 6;        // consumer: 0..3 -> q-group (4 rows / pass)
    int kg   = tid & 63;        // consumer: 8 consecutive cols each
    int bh = blockIdx.y;
    int b = bh / Hh, h = bh % Hh;
    int q0 = blockIdx.x * QROWS;

    const int c_lo = half * 256, c_hi = c_lo + 255;

    float rmk[8], rmq[2][4];
#pragma unroll
    for (int c = 0; c < 8; c++) {
        float mv = mask[b * Sq + kg * 8 + c];
        rmk[c] = (mv == -10000.0f) ? 1.0e9f : mv;
    }
#pragma unroll
    for (int p = 0; p < 2; p++)
#pragma unroll
        for (int r = 0; r < 4; r++) {
            float mv = mask[b * Sq + q0 + p * 16 + qg * 4 + r];
            rmq[p][r] = (mv == -10000.0f) ? 1.0e9f : mv;
        }

    const uint32_t sq_b  = smem_u32(sQ);
    const uint32_t skb_b = smem_u32(sKB);

    for (int mode = 0; mode < 3; mode++) {
        const uint32_t* Qp = g_projP + (size_t)((mode * 2) * 2)     * Mrows * PW;
        const uint32_t* Kp = g_projP + (size_t)((mode * 2 + 1) * 2) * Mrows * PW;

        int tc_lo, tc_hi;
        if (mode == 0)      { tc_lo = 0;         tc_hi = (q0 + 31) / 128 + 1; }
        else if (mode == 1) { tc_lo = q0 >> 7;   tc_hi = 4; }
        else                { tc_lo = 0;         tc_hi = 4; }

        auto stageK = [&](int tc, int buf) {
            const uint32_t kb = skb_b + (uint32_t)(buf * KBUF) * 4;
#pragma unroll
            for (int i = 0; i < 8; i++) {
                int id = i * 256 + tid;           // 0..2047
                int tokl = id >> 4;               // 0..127
                int rem = id & 15;
                int plane = rem >> 3;
                int qw = (rem & 7) * 4;
                cp16(kb + (uint32_t)(plane * 4608 + tokl * 36 + qw) * 4,
                     &Kp[(size_t)plane * Mrows * PW +
                         (size_t)(b * Sq + tc * 128 + tokl) * PW + h * 32 + qw]);
            }
            cp_commit();
        };

        __syncthreads();   // protect sQ/sS reuse from previous mode
        {   // stage Q: 2 planes x 32 rows x 32 words
#pragma unroll
            for (int i = 0; i < 2; i++) {
                int id = i * 256 + tid;
                int plane = id >> 8, rem = id & 255;
                int row = rem >> 3, qw = (rem & 7) * 4;
                cp16(sq_b + (uint32_t)(plane * 1152 + row * 36 + qw) * 4,
                     &Qp[(size_t)plane * Mrows * PW +
                         (size_t)(b * Sq + q0 + row) * PW + h * 32 + qw]);
            }
        }
        stageK(tc_lo, 0);   // commits Q + first K chunk

        for (int tc = tc_lo; tc < tc_hi; tc++) {
            const int bufc = (tc - tc_lo) & 1;
            if (tc + 1 < tc_hi) { stageK(tc + 1, bufc ^ 1); cp_wait<1>(); }
            else                { cp_wait<0>(); }
            __syncthreads();

            const int cb = tc * 128;
            const bool warp_do =
                (mode == 0) ? (cb + ct * 32 <= q0 + 31) :
                (mode == 1) ? (cb + ct * 32 + 31 >= q0) : true;
            if (warp_do) {
                float accp[4][4];
#pragma unroll
                for (int nf = 0; nf < 4; nf++)
#pragma unroll
                    for (int i = 0; i < 4; i++) accp[nf][i] = 0.0f;
                const uint32_t* kbuf = sKB + bufc * KBUF;
                const int r0 = rt * 16 + g;
#pragma unroll
                for (int ks = 0; ks < 4; ks++) {
                    const int qw = ks * 8;
                    uint32_t ah[4], al[4];
                    ah[0] = sQ[r0 * 36 + qw + t];
                    ah[1] = sQ[(r0 + 8) * 36 + qw + t];
                    ah[2] = sQ[r0 * 36 + qw + t + 4];
                    ah[3] = sQ[(r0 + 8) * 36 + qw + t + 4];
                    al[0] = sQ[1152 + r0 * 36 + qw + t];
                    al[1] = sQ[1152 + (r0 + 8) * 36 + qw + t];
                    al[2] = sQ[1152 + r0 * 36 + qw + t + 4];
                    al[3] = sQ[1152 + (r0 + 8) * 36 + qw + t + 4];
#pragma unroll
                    for (int nf = 0; nf < 4; nf++) {
                        int n = ct * 32 + nf * 8 + g;
                        uint32_t bhv[2], blv[2];
                        bhv[0] = kbuf[n * 36 + qw + t];
                        bhv[1] = kbuf[n * 36 + qw + t + 4];
                        blv[0] = kbuf[4608 + n * 36 + qw + t];
                        blv[1] = kbuf[4608 + n * 36 + qw + t + 4];
                        mma16(accp[nf], ah, bhv);
                        mma16(accp[nf], ah, blv);
                        mma16(accp[nf], al, bhv);
                    }
                }
#pragma unroll
                for (int nf = 0; nf < 4; nf++) {
                    int col = cb + ct * 32 + nf * 8 + 2 * t;
                    *(float2*)&sS[(rt * 16 + g) * SS_STR + col] =
                        make_float2(accp[nf][0], accp[nf][1]);
                    *(float2*)&sS[(rt * 16 + 8 + g) * SS_STR + col] =
                        make_float2(accp[nf][2], accp[nf][3]);
                }
            }
            __syncthreads();
        }

        // ---------------- consumer: two passes of 16 rows ----------------
        if (mode < 2) {
#pragma unroll
            for (int p = 0; p < 2; p++) {
                const int lro = p * 16 + qg * 4;
                const int qminp = q0 + lro;
                const bool skipc = (mode == 0 && c_lo > qminp + 3) ||
                                   (mode == 1 && c_hi < qminp);
                float acc[4][8];
                float tval[4];
#pragma unroll
                for (int r = 0; r < 4; r++) {
                    if (skipc) {
#pragma unroll
                        for (int c = 0; c < 8; c++) acc[r][c] = 0.0f;
                        tval[r] = 0.0f;
                        if (lane == 31) sRed[(qg * 4 + r) * 2 + half] = 0.0f;
                    } else {
                        const float* srow = &sS[(lro + r) * SS_STR + kg * 8];
                        float4 s0 = *(const float4*)&srow[0];
                        float4 s1 = *(const float4*)&srow[4];
                        acc[r][0] = s0.x; acc[r][1] = s0.y; acc[r][2] = s0.z; acc[r][3] = s0.w;
                        acc[r][4] = s1.x; acc[r][5] = s1.y; acc[r][6] = s1.z; acc[r][7] = s1.w;
                        int q = qminp + r;
                        if (mode == 0) {
#pragma unroll
                            for (int c = 0; c < 8; c++)
                                if (kg * 8 + c > q) acc[r][c] = -1.0e9f;   // absolute
                        } else {
#pragma unroll
                            for (int c = 0; c < 8; c++)
                                if (kg * 8 + c < q) acc[r][c] = -1.0e9f;   // absolute
                        }
                        float run = 0.0f;
#pragma unroll
                        for (int c = 0; c < 8; c++) {
                            run += __expf(acc[r][c]);
                            acc[r][c] = run;
                        }
                        float tv = run;
#pragma unroll
                        for (int off = 1; off < 32; off <<= 1) {
                            float u = __shfl_up_sync(0xffffffffu, tv, off);
                            if (lane >= off) tv += u;
                        }
                        tval[r] = tv;
                        if (lane == 31) sRed[(qg * 4 + r) * 2 + half] = tv;
                    }
                }
                __syncthreads();
#pragma unroll
                for (int r = 0; r < 4; r++) {
                    float w0 = sRed[(qg * 4 + r) * 2 + 0], w1 = sRed[(qg * 4 + r) * 2 + 1];
                    float sumrow = w0 + w1;
                    float tot = acc[r][7];
                    float excl = (half ? w0 : 0.0f) + (tval[r] - tot);
                    float inv = 1.0f / sumrow;
                    float* mrow_p = &sMK[(lro + r) * 512 + kg * 8];
                    if (mode == 0) {
                        float v[8];
#pragma unroll
                        for (int c = 0; c < 8; c++)
                            v[c] = (excl + acc[r][c]) * inv;
                        *(float4*)&mrow_p[0] = make_float4(v[0], v[1], v[2], v[3]);
                        *(float4*)&mrow_p[4] = make_float4(v[4], v[5], v[6], v[7]);
                    } else {
                        float4 m0 = *(const float4*)&mrow_p[0];
                        float4 m1 = *(const float4*)&mrow_p[4];
                        float m[8] = {m0.x, m0.y, m0.z, m0.w, m1.x, m1.y, m1.z, m1.w};
                        float base = sumrow - excl;
                        m[0] *= base * inv;
#pragma unroll
                        for (int c = 1; c < 8; c++)
                            m[c] *= (base - acc[r][c - 1]) * inv;
                        *(float4*)&mrow_p[0] = make_float4(m[0], m[1], m[2], m[3]);
                        *(float4*)&mrow_p[4] = make_float4(m[4], m[5], m[6], m[7]);
                    }
                }
                __syncthreads();
            }
        } else {
            float lsum = 0.0f;
#pragma unroll
            for (int p = 0; p < 2; p++) {
                const int lro = p * 16 + qg * 4;
                const int qminp = q0 + lro;
                float acc[4][8];
#pragma unroll
                for (int r = 0; r < 4; r++) {
                    const float* srow = &sS[(lro + r) * SS_STR + kg * 8];
                    float4 s0 = *(const float4*)&srow[0];
                    float4 s1 = *(const float4*)&srow[4];
                    acc[r][0] = s0.x; acc[r][1] = s0.y; acc[r][2] = s0.z; acc[r][3] = s0.w;
                    acc[r][4] = s1.x; acc[r][5] = s1.y; acc[r][6] = s1.z; acc[r][7] = s1.w;
                    const float* mrow_p = &sMK[(lro + r) * 512 + kg * 8];
                    float4 m0 = *(const float4*)&mrow_p[0];
                    float4 m1 = *(const float4*)&mrow_p[4];
                    float m[8] = {m0.x, m0.y, m0.z, m0.w, m1.x, m1.y, m1.z, m1.w};
#pragma unroll
                    for (int c = 0; c < 8; c++)
                        acc[r][c] = (acc[r][c] - rmq[p][r] - rmk[c]) * m[c];
                }
                // max-subtraction (required: padded rows)
                float mrow[4];
#pragma unroll
                for (int r = 0; r < 4; r++) {
                    float m = acc[r][0];
#pragma unroll
                    for (int c = 1; c < 8; c++) m = fmaxf(m, acc[r][c]);
#pragma unroll
                    for (int off = 16; off >= 1; off >>= 1)
                        m = fmaxf(m, __shfl_xor_sync(0xffffffffu, m, off));
                    if (lane == 0) sRed[(qg * 4 + r) * 2 + half] = m;
                }
                __syncthreads();
#pragma unroll
                for (int r = 0; r < 4; r++)
                    mrow[r] = fmaxf(sRed[(qg * 4 + r) * 2 + 0], sRed[(qg * 4 + r) * 2 + 1]);
                __syncthreads();

#pragma unroll
                for (int r = 0; r < 4; r++) {
                    float s = 0.0f;
#pragma unroll
                    for (int c = 0; c < 8; c++) {
                        acc[r][c] = __expf(acc[r][c] - mrow[r]);
                        s += acc[r][c];
                    }
#pragma unroll
                    for (int off = 16; off >= 1; off >>= 1)
                        s += __shfl_xor_sync(0xffffffffu, s, off);
                    if (lane == 0) sRed[(qg * 4 + r) * 2 + half] = s;
                }
                __syncthreads();
#pragma unroll
                for (int r = 0; r < 4; r++) {
                    int q = qminp + r;
                    float inv = 1.0f / (sRed[(qg * 4 + r) * 2 + 0] + sRed[(qg * 4 + r) * 2 + 1]);
                    size_t oidx = ((size_t)bh * Sq + q) * Sq + kg * 8;
                    size_t sidx = ((size_t)((h * Bq + b) * Sq + q)) * Sq + kg * 8;
                    float4 sp0 = *(const float4*)&span[sidx];
                    float4 sp1 = *(const float4*)&span[sidx + 4];
                    float sp[8] = {sp0.x, sp0.y, sp0.z, sp0.w, sp1.x, sp1.y, sp1.z, sp1.w};
                    float pv[8];
#pragma unroll
                    for (int c = 0; c < 8; c++) pv[c] = acc[r][c] * inv;
                    float4 o0 = {pv[0], pv[1], pv[2], pv[3]};
                    float4 o1 = {pv[4], pv[5], pv[6], pv[7]};
                    *(float4*)&out[oidx]     = o0;
                    *(float4*)&out[oidx + 4] = o1;
#pragma unroll
                    for (int c = 0; c < 8; c++)
                        lsum += softplus_neg01(pv[c]) + pv[c] * (1.0f - sp[c]);
                }
                __syncthreads();
            }
#pragma unroll
            for (int off = 16; off >= 1; off >>= 1)
                lsum += __shfl_xor_sync(0xffffffffu, lsum, off);
            if (lane == 0) sW[warp] = lsum;
            __syncthreads();
            if (tid == 0) {
                float tot = 0.0f;
#pragma unroll
                for (int ww = 0; ww < 8; ww++) tot += sW[ww];
                atomicAdd(&g_loss, (double)tot);
            }
        }
    }
}

__global__ void finalize_kernel(float* out, int out_size) {
    if (out_size > NATT)
        out[NATT] = (float)(g_loss / (double)NATT);
}

// ---------------------------------------------------------------------------
extern "C" void kernel_launch(void* const* d_in, const int* in_sizes, int n_in,
                              void* d_out, int out_size)
{
    (void)in_sizes; (void)n_in;
    const float* query = (const float*)d_in[0];
    const float* key   = (const float*)d_in[1];
    const float* mask  = (const float*)d_in[2];
    const float* span  = (const float*)d_in[3];
    float* out = (float*)d_out;

    Ptr6 ws, bs;
    for (int w = 0; w < 6; w++) {
        ws.p[w] = (const float*)d_in[4 + 2 * w];
        bs.p[w] = (const float*)d_in[5 + 2 * w];
    }

    cudaFuncSetAttribute(gemm_mma, cudaFuncAttributeMaxDynamicSharedMemorySize, DYN_SMEM);
    cudaFuncSetAttribute(attn_fused, cudaFuncAttributeMaxDynamicSharedMemorySize, ATTN_SMEM_BYTES);

    pack_qk<<<dim3(Mrows * PW / 256, 2), 256>>>(query, key);
    transpose_pack6<<<dim3(Dm / 32, Dm / 32, 6), dim3(32, 8)>>>(ws);
    gemm_mma<<<dim3(Mrows / BM, Dm / BN, 6), 256, DYN_SMEM>>>(bs);
    attn_fused<<<dim3(Sq / QROWS, BHn), 256, ATTN_SMEM_BYTES>>>(mask, span, out);
    finalize_kernel<<<1, 1>>>(out, out_size);
}

// round 13
// speedup vs baseline: 2.4129x; 1.0920x over previous
#include <cuda_runtime.h>
#include <cstdint>
#include <math.h>

#define Bq    8
#define Sq    512
#define Dm    768
#define Hh    12
#define Dk    64
#define BHn   (Bq*Hh)            // 96
#define Mrows (Bq*Sq)            // 4096
#define NATT  (25165824)         // B*H*S*S
#define SCALE 0.036084391824351615f   // 1/sqrt(768)
#define PW    384                // packed words per row (Dm/2)

// ---- projection GEMM tiling (bf16 m16n8k16, 3x split) ----
#define BM 128
#define BN 64
#define APL 2560                 // A plane words per stage: 128*20
#define BPL 1280                 // B plane words per stage: 64*20
#define STAGE_W (2*APL + 2*BPL)  // 7680 words
#define DYN_SMEM (2*STAGE_W*4)   // 61440 bytes
#define NSTAGE (Dm/32)           // 24

// ---- attn smem layout (4B words), 32 q-rows per block ----
#define QROWS 32
#define KBUF  9216               // K chunk buffer: 2 planes x 128 tok x 36 words
#define SS_STR 520
#define OFF_SQ   0                               // 2 planes x 32 x 36 = 2304
#define OFF_SKB  2304                            // 2 bufs x 9216 = 18432
#define OFF_SS   20736                           // 32 x 520 = 16640
#define OFF_SMK  37376                           // 32 x 512 = 16384
#define OFF_RED  53760                           // 32
#define OFF_W    53792                           // 8
#define ATTN_SMEM_BYTES  ((OFF_W + 8)*4)         // 215200

// Scratch (device globals: allocation-free, graph-capturable)
__device__ uint32_t g_qkP[(size_t)2 * 2 * Mrows * PW];   // [mat][plane] query,key packed
__device__ uint32_t g_wP[(size_t)6 * 2 * Dm * PW];       // [w][plane] W^T packed
__device__ uint32_t g_projP[(size_t)6 * 2 * Mrows * PW]; // [w][plane] projections packed
__device__ double g_loss;

struct Ptr6 { const float* p[6]; };

// ---------------------------------------------------------------------------
// helpers
// ---------------------------------------------------------------------------
__device__ __forceinline__ uint32_t smem_u32(const void* p) {
    uint32_t a;
    asm("{ .reg .u64 t; cvta.to.shared.u64 t, %1; cvt.u32.u64 %0, t; }"
        : "=r"(a) : "l"(p));
    return a;
}
__device__ __forceinline__ void cp16(uint32_t s, const void* g) {
    asm volatile("cp.async.ca.shared.global [%0], [%1], 16;"
                 :: "r"(s), "l"(g) : "memory");
}
__device__ __forceinline__ void cp_commit() {
    asm volatile("cp.async.commit_group;" ::: "memory");
}
template <int N>
__device__ __forceinline__ void cp_wait() {
    asm volatile("cp.async.wait_group %0;" :: "n"(N) : "memory");
}
// ldmatrix x4: one instr loads 4 fragment registers
__device__ __forceinline__ void ldsm4(uint32_t* r, uint32_t addr) {
    asm volatile("ldmatrix.sync.aligned.m8n8.x4.shared.b16 {%0,%1,%2,%3}, [%4];"
        : "=r"(r[0]), "=r"(r[1]), "=r"(r[2]), "=r"(r[3]) : "r"(addr));
}
// bf16 hi/lo split (bit ops only; Sterbenz => a-hi exact)
__device__ __forceinline__ void splitb(float a, uint32_t& hb, uint32_t& lb) {
    uint32_t u = __float_as_uint(a);
    hb = u & 0xFFFF0000u;
    float l = a - __uint_as_float(hb);
    lb = __float_as_uint(l) & 0xFFFF0000u;
}
__device__ __forceinline__ uint32_t packw(uint32_t b0, uint32_t b1) {
    return b1 | (b0 >> 16);
}
__device__ __forceinline__ void mma16(float* c, const uint32_t* a, const uint32_t* b) {
    asm volatile(
        "mma.sync.aligned.m16n8k16.row.col.f32.bf16.bf16.f32 "
        "{%0,%1,%2,%3}, {%4,%5,%6,%7}, {%8,%9}, {%0,%1,%2,%3};"
        : "+f"(c[0]), "+f"(c[1]), "+f"(c[2]), "+f"(c[3])
        : "r"(a[0]), "r"(a[1]), "r"(a[2]), "r"(a[3]), "r"(b[0]), "r"(b[1]));
}
// ln(1+e^-p) for p in [0,1], no MUFU (Taylor, err ~1.5e-8)
__device__ __forceinline__ float softplus_neg01(float p) {
    float x = 0.5f * p;
    float y = x * x;
    float lc = y * (0.5f + y * (-8.3333333333e-2f + y * (2.2222222222e-2f +
               y * (-6.7460317460e-3f + y * (2.1869488536e-3f +
               y * (-7.3860295563e-4f))))));
    return 0.69314718056f - x + lc;
}

// ---------------------------------------------------------------------------
// Pack query/key into bf16 hi/lo planes (also zeroes g_loss).
// ---------------------------------------------------------------------------
__global__ void pack_qk(const float* __restrict__ query, const float* __restrict__ key) {
    if (blockIdx.x == 0 && blockIdx.y == 0 && threadIdx.x == 0) g_loss = 0.0;
    int mat = blockIdx.y;
    const float* src = mat ? key : query;
    uint32_t* hi = g_qkP + (size_t)(mat * 2 + 0) * Mrows * PW;
    uint32_t* lo = g_qkP + (size_t)(mat * 2 + 1) * Mrows * PW;
    int idx = blockIdx.x * 256 + threadIdx.x;
    float2 v = *(const float2*)&src[(size_t)idx * 2];
    uint32_t h0, l0, h1, l1;
    splitb(v.x, h0, l0);
    splitb(v.y, h1, l1);
    hi[idx] = packw(h0, h1);
    lo[idx] = packw(l0, l1);
}

// ---------------------------------------------------------------------------
// Transpose + pack all 6 weight matrices as bf16 hi/lo planes (n-major).
// ---------------------------------------------------------------------------
__global__ void transpose_pack6(Ptr6 ws) {
    __shared__ float t[32][33];
    int w = blockIdx.z;
    const float* W = ws.p[w];
    uint32_t* Thi = g_wP + (size_t)(w * 2 + 0) * Dm * PW;
    uint32_t* Tlo = g_wP + (size_t)(w * 2 + 1) * Dm * PW;
    int n0 = blockIdx.x * 32, k0 = blockIdx.y * 32;
    int tid = threadIdx.y * 32 + threadIdx.x;
#pragma unroll
    for (int i = 0; i < 4; i++)
        t[threadIdx.y + i * 8][threadIdx.x] =
            W[(size_t)(k0 + threadIdx.y + i * 8) * Dm + n0 + threadIdx.x];
    __syncthreads();
#pragma unroll
    for (int i = 0; i < 2; i++) {
        int lin = i * 256 + tid;
        int n = lin >> 4, j = lin & 15;
        uint32_t h0, l0, h1, l1;
        splitb(t[2 * j][n],     h0, l0);
        splitb(t[2 * j + 1][n], h1, l1);
        size_t idx = (size_t)(n0 + n) * PW + k0 / 2 + j;
        Thi[idx] = packw(h0, h1);
        Tlo[idx] = packw(l0, l1);
    }
}

// ---------------------------------------------------------------------------
// bf16 m16n8k16 GEMM (3x split), ldmatrix fragment loads.
// ---------------------------------------------------------------------------
__global__ __launch_bounds__(256, 2) void gemm_mma(Ptr6 biases)
{
    extern __shared__ uint32_t dsw[];
    const int tid = threadIdx.x, warp = tid >> 5, lane = tid & 31;
    const int g = lane >> 2, t = lane & 3;
    const int wm = (warp >> 1) * 32, wn = (warp & 1) * 32;
    // ldmatrix per-lane offsets
    const int a_r = ((lane >> 3) & 1) * 8 + (lane & 7);
    const int a_w = (lane >> 4) * 4;
    const int b_r = (lane >> 4) * 8 + (lane & 7);
    const int b_w = ((lane >> 3) & 1) * 4;

    const int w = blockIdx.z;
    const int mat = w & 1;
    const uint32_t* Asrc = g_qkP + (size_t)(mat * 2) * Mrows * PW;
    const uint32_t* Bsrc = g_wP + (size_t)(w * 2) * Dm * PW;
    uint32_t* Phi = g_projP + (size_t)(w * 2 + 0) * Mrows * PW;
    uint32_t* Plo = g_projP + (size_t)(w * 2 + 1) * Mrows * PW;
    const float* bias = biases.p[w];
    const float scale = mat ? 1.0f : SCALE;
    const int m0 = blockIdx.x * BM, n0 = blockIdx.y * BN;

    const uint32_t sb = smem_u32(dsw);

    auto load_stage = [&](int s, int buf) {
        const int kw = s * 16;
        const uint32_t base = sb + (uint32_t)buf * STAGE_W * 4;
#pragma unroll
        for (int i = 0; i < 4; i++) {
            int id = i * 256 + tid;
            int plane = id >> 9, rem = id & 511;
            int row = rem >> 2, q = rem & 3;
            cp16(base + (uint32_t)(plane * APL + row * 20 + q * 4) * 4,
                 &Asrc[(size_t)plane * Mrows * PW + (size_t)(m0 + row) * PW + kw + q * 4]);
        }
#pragma unroll
        for (int i = 0; i < 2; i++) {
            int id = i * 256 + tid;
            int plane = id >> 8, rem = id & 255;
            int row = rem >> 2, q = rem & 3;
            cp16(base + (uint32_t)(2 * APL + plane * BPL + row * 20 + q * 4) * 4,
                 &Bsrc[(size_t)plane * Dm * PW + (size_t)(n0 + row) * PW + kw + q * 4]);
        }
        cp_commit();
    };

    float acc[2][4][4];
#pragma unroll
    for (int mf = 0; mf < 2; mf++)
#pragma unroll
        for (int nf = 0; nf < 4; nf++)
#pragma unroll
            for (int i = 0; i < 4; i++) acc[mf][nf][i] = 0.0f;

    load_stage(0, 0);

    for (int s = 0; s < NSTAGE; s++) {
        if (s + 1 < NSTAGE) { load_stage(s + 1, (s + 1) & 1); cp_wait<1>(); }
        else                { cp_wait<0>(); }
        __syncthreads();

        const uint32_t st_b = sb + (uint32_t)(s & 1) * STAGE_W * 4;

#pragma unroll
        for (int ks = 0; ks < 2; ks++) {
            const int kw = ks * 8;
            uint32_t ah[2][4], al[2][4], bfr[2][4], blr[2][4];
#pragma unroll
            for (int mf = 0; mf < 2; mf++) {
                uint32_t aaddr = st_b +
                    (uint32_t)((wm + mf * 16 + a_r) * 20 + kw + a_w) * 4;
                ldsm4(ah[mf], aaddr);
                ldsm4(al[mf], aaddr + APL * 4);
            }
#pragma unroll
            for (int np = 0; np < 2; np++) {   // each covers 2 n-tiles
                uint32_t baddr = st_b + (uint32_t)(2 * APL) * 4 +
                    (uint32_t)((wn + np * 16 + b_r) * 20 + kw + b_w) * 4;
                ldsm4(bfr[np], baddr);
                ldsm4(blr[np], baddr + BPL * 4);
            }
#pragma unroll
            for (int mf = 0; mf < 2; mf++)
#pragma unroll
                for (int nf = 0; nf < 4; nf++) {
                    const uint32_t* bh = &bfr[nf >> 1][(nf & 1) * 2];
                    const uint32_t* bl = &blr[nf >> 1][(nf & 1) * 2];
                    mma16(acc[mf][nf], ah[mf], bh);
                    mma16(acc[mf][nf], ah[mf], bl);
                    mma16(acc[mf][nf], al[mf], bh);
                }
        }
        __syncthreads();
    }

#pragma unroll
    for (int mf = 0; mf < 2; mf++) {
        int row0 = m0 + wm + mf * 16 + g;
#pragma unroll
        for (int nf = 0; nf < 4; nf++) {
            int col = n0 + wn + nf * 8 + 2 * t;
            int wcol = (n0 + wn + nf * 8) / 2 + t;
            float2 bv = *(const float2*)&bias[col];
            float v00 = (acc[mf][nf][0] + bv.x) * scale;
            float v01 = (acc[mf][nf][1] + bv.y) * scale;
            float v10 = (acc[mf][nf][2] + bv.x) * scale;
            float v11 = (acc[mf][nf][3] + bv.y) * scale;
            uint32_t h0, l0, h1, l1;
            splitb(v00, h0, l0); splitb(v01, h1, l1);
            Phi[(size_t)row0 * PW + wcol] = packw(h0, h1);
            Plo[(size_t)row0 * PW + wcol] = packw(l0, l1);
            splitb(v10, h0, l0); splitb(v11, h1, l1);
            Phi[(size_t)(row0 + 8) * PW + wcol] = packw(h0, h1);
            Plo[(size_t)(row0 + 8) * PW + wcol] = packw(l0, l1);
        }
    }
}

// ---------------------------------------------------------------------------
// Fused attention: 32 q-rows per block, token-chunked K staging, chunk
// skipping, smk in smem, two-pass consumer. ldmatrix fragment loads.
// ---------------------------------------------------------------------------
__global__ __launch_bounds__(256) void attn_fused(
    const float* __restrict__ mask,
    const float* __restrict__ span, float* __restrict__ out)
{
    extern __shared__ uint32_t smw[];
    uint32_t* sQ  = smw + OFF_SQ;
    uint32_t* sKB = smw + OFF_SKB;
    float* sS  = (float*)(smw + OFF_SS);
    float* sMK = (float*)(smw + OFF_SMK);
    float* sRed= (float*)(smw + OFF_RED);
    float* sW  = (float*)(smw + OFF_W);

    int tid  = threadIdx.x;
    int lane = tid & 31;
    int warp = tid >> 5;        // 0..7
    int g    = lane >> 2, t = lane & 3;
    int rt   = warp >> 2;       // producer row tile (0/1)
    int ct   = warp & 3;        // producer 32-col tile within 128-token chunk
    int half = (tid >> 5) & 1;  // consumer: which 256-col half
    int qg   = tid >> 6;        // consumer: 0..3 -> q-group (4 rows / pass)
    int kg   = tid & 63;        // consumer: 8 consecutive cols each
    // ldmatrix per-lane offsets
    const int a_r = ((lane >> 3) & 1) * 8 + (lane & 7);
    const int a_w = (lane >> 4) * 4;
    const int b_r = (lane >> 4) * 8 + (lane & 7);
    const int b_w = ((lane >> 3) & 1) * 4;

    int bh = blockIdx.y;
    int b = bh / Hh, h = bh % Hh;
    int q0 = blockIdx.x * QROWS;

    const int c_lo = half * 256, c_hi = c_lo + 255;

    float rmk[8], rmq[2][4];
#pragma unroll
    for (int c = 0; c < 8; c++) {
        float mv = mask[b * Sq + kg * 8 + c];
        rmk[c] = (mv == -10000.0f) ? 1.0e9f : mv;
    }
#pragma unroll
    for (int p = 0; p < 2; p++)
#pragma unroll
        for (int r = 0; r < 4; r++) {
            float mv = mask[b * Sq + q0 + p * 16 + qg * 4 + r];
            rmq[p][r] = (mv == -10000.0f) ? 1.0e9f : mv;
        }

    const uint32_t sq_b  = smem_u32(sQ);
    const uint32_t skb_b = smem_u32(sKB);

    for (int mode = 0; mode < 3; mode++) {
        const uint32_t* Qp = g_projP + (size_t)((mode * 2) * 2)     * Mrows * PW;
        const uint32_t* Kp = g_projP + (size_t)((mode * 2 + 1) * 2) * Mrows * PW;

        int tc_lo, tc_hi;
        if (mode == 0)      { tc_lo = 0;         tc_hi = (q0 + 31) / 128 + 1; }
        else if (mode == 1) { tc_lo = q0 >> 7;   tc_hi = 4; }
        else                { tc_lo = 0;         tc_hi = 4; }

        auto stageK = [&](int tc, int buf) {
            const uint32_t kb = skb_b + (uint32_t)(buf * KBUF) * 4;
#pragma unroll
            for (int i = 0; i < 8; i++) {
                int id = i * 256 + tid;
                int tokl = id >> 4;
                int rem = id & 15;
                int plane = rem >> 3;
                int qw = (rem & 7) * 4;
                cp16(kb + (uint32_t)(plane * 4608 + tokl * 36 + qw) * 4,
                     &Kp[(size_t)plane * Mrows * PW +
                         (size_t)(b * Sq + tc * 128 + tokl) * PW + h * 32 + qw]);
            }
            cp_commit();
        };

        __syncthreads();   // protect sQ/sS reuse from previous mode
        {
#pragma unroll
            for (int i = 0; i < 2; i++) {
                int id = i * 256 + tid;
                int plane = id >> 8, rem = id & 255;
                int row = rem >> 3, qw = (rem & 7) * 4;
                cp16(sq_b + (uint32_t)(plane * 1152 + row * 36 + qw) * 4,
                     &Qp[(size_t)plane * Mrows * PW +
                         (size_t)(b * Sq + q0 + row) * PW + h * 32 + qw]);
            }
        }
        stageK(tc_lo, 0);

        for (int tc = tc_lo; tc < tc_hi; tc++) {
            const int bufc = (tc - tc_lo) & 1;
            if (tc + 1 < tc_hi) { stageK(tc + 1, bufc ^ 1); cp_wait<1>(); }
            else                { cp_wait<0>(); }
            __syncthreads();

            const int cb = tc * 128;
            const bool warp_do =
                (mode == 0) ? (cb + ct * 32 <= q0 + 31) :
                (mode == 1) ? (cb + ct * 32 + 31 >= q0) : true;
            if (warp_do) {
                float accp[4][4];
#pragma unroll
                for (int nf = 0; nf < 4; nf++)
#pragma unroll
                    for (int i = 0; i < 4; i++) accp[nf][i] = 0.0f;
                const uint32_t kbb = skb_b + (uint32_t)(bufc * KBUF) * 4;
#pragma unroll
                for (int ks = 0; ks < 4; ks++) {
                    const int qw = ks * 8;
                    uint32_t ah[4], al[4], bfr[2][4], blr[2][4];
                    uint32_t aaddr = sq_b +
                        (uint32_t)((rt * 16 + a_r) * 36 + qw + a_w) * 4;
                    ldsm4(ah, aaddr);
                    ldsm4(al, aaddr + 1152 * 4);
#pragma unroll
                    for (int np = 0; np < 2; np++) {
                        uint32_t baddr = kbb +
                            (uint32_t)((ct * 32 + np * 16 + b_r) * 36 + qw + b_w) * 4;
                        ldsm4(bfr[np], baddr);
                        ldsm4(blr[np], baddr + 4608 * 4);
                    }
#pragma unroll
                    for (int nf = 0; nf < 4; nf++) {
                        const uint32_t* bhv = &bfr[nf >> 1][(nf & 1) * 2];
                        const uint32_t* blv = &blr[nf >> 1][(nf & 1) * 2];
                        mma16(accp[nf], ah, bhv);
                        mma16(accp[nf], ah, blv);
                        mma16(accp[nf], al, bhv);
                    }
                }
#pragma unroll
                for (int nf = 0; nf < 4; nf++) {
                    int col = cb + ct * 32 + nf * 8 + 2 * t;
                    *(float2*)&sS[(rt * 16 + g) * SS_STR + col] =
                        make_float2(accp[nf][0], accp[nf][1]);
                    *(float2*)&sS[(rt * 16 + 8 + g) * SS_STR + col] =
                        make_float2(accp[nf][2], accp[nf][3]);
                }
            }
            __syncthreads();
        }

        // ---------------- consumer: two passes of 16 rows ----------------
        if (mode < 2) {
#pragma unroll
            for (int p = 0; p < 2; p++) {
                const int lro = p * 16 + qg * 4;
                const int qminp = q0 + lro;
                const bool skipc = (mode == 0 && c_lo > qminp + 3) ||
                                   (mode == 1 && c_hi < qminp);
                float acc[4][8];
                float tval[4];
#pragma unroll
                for (int r = 0; r < 4; r++) {
                    if (skipc) {
#pragma unroll
                        for (int c = 0; c < 8; c++) acc[r][c] = 0.0f;
                        tval[r] = 0.0f;
                        if (lane == 31) sRed[(qg * 4 + r) * 2 + half] = 0.0f;
                    } else {
                        const float* srow = &sS[(lro + r) * SS_STR + kg * 8];
                        float4 s0 = *(const float4*)&srow[0];
                        float4 s1 = *(const float4*)&srow[4];
                        acc[r][0] = s0.x; acc[r][1] = s0.y; acc[r][2] = s0.z; acc[r][3] = s0.w;
                        acc[r][4] = s1.x; acc[r][5] = s1.y; acc[r][6] = s1.z; acc[r][7] = s1.w;
                        int q = qminp + r;
                        if (mode == 0) {
#pragma unroll
                            for (int c = 0; c < 8; c++)
                                if (kg * 8 + c > q) acc[r][c] = -1.0e9f;
                        } else {
#pragma unroll
                            for (int c = 0; c < 8; c++)
                                if (kg * 8 + c < q) acc[r][c] = -1.0e9f;
                        }
                        float run = 0.0f;
#pragma unroll
                        for (int c = 0; c < 8; c++) {
                            run += __expf(acc[r][c]);
                            acc[r][c] = run;
                        }
                        float tv = run;
#pragma unroll
                        for (int off = 1; off < 32; off <<= 1) {
                            float u = __shfl_up_sync(0xffffffffu, tv, off);
                            if (lane >= off) tv += u;
                        }
                        tval[r] = tv;
                        if (lane == 31) sRed[(qg * 4 + r) * 2 + half] = tv;
                    }
                }
                __syncthreads();
#pragma unroll
                for (int r = 0; r < 4; r++) {
                    float w0 = sRed[(qg * 4 + r) * 2 + 0], w1 = sRed[(qg * 4 + r) * 2 + 1];
                    float sumrow = w0 + w1;
                    float tot = acc[r][7];
                    float excl = (half ? w0 : 0.0f) + (tval[r] - tot);
                    float inv = 1.0f / sumrow;
                    float* mrow_p = &sMK[(lro + r) * 512 + kg * 8];
                    if (mode == 0) {
                        float v[8];
#pragma unroll
                        for (int c = 0; c < 8; c++)
                            v[c] = (excl + acc[r][c]) * inv;
                        *(float4*)&mrow_p[0] = make_float4(v[0], v[1], v[2], v[3]);
                        *(float4*)&mrow_p[4] = make_float4(v[4], v[5], v[6], v[7]);
                    } else {
                        float4 m0 = *(const float4*)&mrow_p[0];
                        float4 m1 = *(const float4*)&mrow_p[4];
                        float m[8] = {m0.x, m0.y, m0.z, m0.w, m1.x, m1.y, m1.z, m1.w};
                        float base = sumrow - excl;
                        m[0] *= base * inv;
#pragma unroll
                        for (int c = 1; c < 8; c++)
                            m[c] *= (base - acc[r][c - 1]) * inv;
                        *(float4*)&mrow_p[0] = make_float4(m[0], m[1], m[2], m[3]);
                        *(float4*)&mrow_p[4] = make_float4(m[4], m[5], m[6], m[7]);
                    }
                }
                __syncthreads();
            }
        } else {
            float lsum = 0.0f;
#pragma unroll
            for (int p = 0; p < 2; p++) {
                const int lro = p * 16 + qg * 4;
                const int qminp = q0 + lro;
                float acc[4][8];
#pragma unroll
                for (int r = 0; r < 4; r++) {
                    const float* srow = &sS[(lro + r) * SS_STR + kg * 8];
                    float4 s0 = *(const float4*)&srow[0];
                    float4 s1 = *(const float4*)&srow[4];
                    acc[r][0] = s0.x; acc[r][1] = s0.y; acc[r][2] = s0.z; acc[r][3] = s0.w;
                    acc[r][4] = s1.x; acc[r][5] = s1.y; acc[r][6] = s1.z; acc[r][7] = s1.w;
                    const float* mrow_p = &sMK[(lro + r) * 512 + kg * 8];
                    float4 m0 = *(const float4*)&mrow_p[0];
                    float4 m1 = *(const float4*)&mrow_p[4];
                    float m[8] = {m0.x, m0.y, m0.z, m0.w, m1.x, m1.y, m1.z, m1.w};
#pragma unroll
                    for (int c = 0; c < 8; c++)
                        acc[r][c] = (acc[r][c] - rmq[p][r] - rmk[c]) * m[c];
                }
                float mrow[4];
#pragma unroll
                for (int r = 0; r < 4; r++) {
                    float m = acc[r][0];
#pragma unroll
                    for (int c = 1; c < 8; c++) m = fmaxf(m, acc[r][c]);
#pragma unroll
                    for (int off = 16; off >= 1; off >>= 1)
                        m = fmaxf(m, __shfl_xor_sync(0xffffffffu, m, off));
                    if (lane == 0) sRed[(qg * 4 + r) * 2 + half] = m;
                }
                __syncthreads();
#pragma unroll
                for (int r = 0; r < 4; r++)
                    mrow[r] = fmaxf(sRed[(qg * 4 + r) * 2 + 0], sRed[(qg * 4 + r) * 2 + 1]);
                __syncthreads();

#pragma unroll
                for (int r = 0; r < 4; r++) {
                    float s = 0.0f;
#pragma unroll
                    for (int c = 0; c < 8; c++) {
                        acc[r][c] = __expf(acc[r][c] - mrow[r]);
                        s += acc[r][c];
                    }
#pragma unroll
                    for (int off = 16; off >= 1; off >>= 1)
                        s += __shfl_xor_sync(0xffffffffu, s, off);
                    if (lane == 0) sRed[(qg * 4 + r) * 2 + half] = s;
                }
                __syncthreads();
#pragma unroll
                for (int r = 0; r < 4; r++) {
                    int q = qminp + r;
                    float inv = 1.0f / (sRed[(qg * 4 + r) * 2 + 0] + sRed[(qg * 4 + r) * 2 + 1]);
                    size_t oidx = ((size_t)bh * Sq + q) * Sq + kg * 8;
                    size_t sidx = ((size_t)((h * Bq + b) * Sq + q)) * Sq + kg * 8;
                    float4 sp0 = *(const float4*)&span[sidx];
                    float4 sp1 = *(const float4*)&span[sidx + 4];
                    float sp[8] = {sp0.x, sp0.y, sp0.z, sp0.w, sp1.x, sp1.y, sp1.z, sp1.w};
                    float pv[8];
#pragma unroll
                    for (int c = 0; c < 8; c++) pv[c] = acc[r][c] * inv;
                    float4 o0 = {pv[0], pv[1], pv[2], pv[3]};
                    float4 o1 = {pv[4], pv[5], pv[6], pv[7]};
                    *(float4*)&out[oidx]     = o0;
                    *(float4*)&out[oidx + 4] = o1;
#pragma unroll
                    for (int c = 0; c < 8; c++)
                        lsum += softplus_neg01(pv[c]) + pv[c] * (1.0f - sp[c]);
                }
                __syncthreads();
            }
#pragma unroll
            for (int off = 16; off >= 1; off >>= 1)
                lsum += __shfl_xor_sync(0xffffffffu, lsum, off);
            if (lane == 0) sW[warp] = lsum;
            __syncthreads();
            if (tid == 0) {
                float tot = 0.0f;
#pragma unroll
                for (int ww = 0; ww < 8; ww++) tot += sW[ww];
                atomicAdd(&g_loss, (double)tot);
            }
        }
    }
}

__global__ void finalize_kernel(float* out, int out_size) {
    if (out_size > NATT)
        out[NATT] = (float)(g_loss / (double)NATT);
}

// ---------------------------------------------------------------------------
extern "C" void kernel_launch(void* const* d_in, const int* in_sizes, int n_in,
                              void* d_out, int out_size)
{
    (void)in_sizes; (void)n_in;
    const float* query = (const float*)d_in[0];
    const float* key   = (const float*)d_in[1];
    const float* mask  = (const float*)d_in[2];
    const float* span  = (const float*)d_in[3];
    float* out = (float*)d_out;

    Ptr6 ws, bs;
    for (int w = 0; w < 6; w++) {
        ws.p[w] = (const float*)d_in[4 + 2 * w];
        bs.p[w] = (const float*)d_in[5 + 2 * w];
    }

    cudaFuncSetAttribute(gemm_mma, cudaFuncAttributeMaxDynamicSharedMemorySize, DYN_SMEM);
    cudaFuncSetAttribute(attn_fused, cudaFuncAttributeMaxDynamicSharedMemorySize, ATTN_SMEM_BYTES);

    pack_qk<<<dim3(Mrows * PW / 256, 2), 256>>>(query, key);
    transpose_pack6<<<dim3(Dm / 32, Dm / 32, 6), dim3(32, 8)>>>(ws);
    gemm_mma<<<dim3(Mrows / BM, Dm / BN, 6), 256, DYN_SMEM>>>(bs);
    attn_fused<<<dim3(Sq / QROWS, BHn), 256, ATTN_SMEM_BYTES>>>(mask, span, out);
    finalize_kernel<<<1, 1>>>(out, out_size);
}